// round 9
// baseline (speedup 1.0000x reference)
#include <cuda_runtime.h>
#include <cstdint>

// ---------------- problem constants ----------------
// B=16, H=W=64, C=512, NH=16, hd=32, WS=8, N=64, SS=4

// ---------------- device scratch ----------------
__device__ float g_q[1024 * 16 * 64 * 32];
__device__ float g_k[1024 * 16 * 64 * 32];
__device__ float g_v[1024 * 16 * 64 * 32];
__device__ float g_att[65536 * 512];
__device__ float g_bias[16 * 64 * 64];
__device__ float g_x[33554432];   // tf32-pre-rounded query
__device__ float g_wq[786432];    // tf32-pre-rounded qkv_w
__device__ float g_wp[262144];    // tf32-pre-rounded proj_w

// ---------------- helpers ----------------
__device__ __forceinline__ float to_tf32(float x) {
    float r;
    asm("cvt.rna.tf32.f32 %0, %1;" : "=f"(r) : "f"(x));
    return r;
}

__device__ __forceinline__ uint32_t smem_u32(const void* p) {
    uint32_t r;
    asm("{ .reg .u64 t; cvta.to.shared.u64 t, %1; cvt.u32.u64 %0, t; }"
        : "=r"(r) : "l"(p));
    return r;
}

#define MMA8(c, a0, a1, a2, a3, b0, b1)                                      \
    asm volatile(                                                            \
        "mma.sync.aligned.m16n8k8.row.col.f32.tf32.tf32.f32 "                \
        "{%0,%1,%2,%3}, {%4,%5,%6,%7}, {%8,%9}, {%0,%1,%2,%3};\n"            \
        : "+f"((c)[0]), "+f"((c)[1]), "+f"((c)[2]), "+f"((c)[3])             \
        : "r"(a0), "r"(a1), "r"(a2), "r"(a3), "r"(b0), "r"(b1))

#define CP_ASYNC16(dst_u32, src_ptr)                                         \
    asm volatile("cp.async.cg.shared.global [%0], [%1], 16;" ::              \
                 "r"(dst_u32), "l"(src_ptr))
#define CP_COMMIT() asm volatile("cp.async.commit_group;")
#define CP_WAIT0()  asm volatile("cp.async.wait_group 0;")

// window-token row -> original image row (shift + window partition fused).
__device__ __forceinline__ int permute_row(int r) {
    int b   = r >> 12;
    int rem = r & 4095;
    int wi  = rem >> 6, n = rem & 63;
    int hs  = ((wi >> 3) << 3) | (n >> 3);
    int ws  = ((wi & 7) << 3) | (n & 7);
    int hp  = (hs + 4) & 63;
    int wp  = (ws + 4) & 63;
    return (b << 12) | (hp << 6) | wp;
}

// ---------------- K-1: pre-round x / qkv_w / proj_w to tf32 ----------------
__global__ __launch_bounds__(1024) void k_pre(const float* __restrict__ x,
                                              const float* __restrict__ qw,
                                              const float* __restrict__ pw) {
    int i = blockIdx.x * 1024 + threadIdx.x;  // float4 index
    float4 v;
    float4* dst;
    if (i < 8388608) {
        v   = ((const float4*)x)[i];
        dst = &((float4*)g_x)[i];
    } else if (i < 8585216) {
        int j = i - 8388608;
        v   = ((const float4*)qw)[j];
        dst = &((float4*)g_wq)[j];
    } else {
        int j = i - 8585216;
        v   = ((const float4*)pw)[j];
        dst = &((float4*)g_wp)[j];
    }
    float4 r;
    r.x = to_tf32(v.x); r.y = to_tf32(v.y);
    r.z = to_tf32(v.z); r.w = to_tf32(v.w);
    *dst = r;
}

// ---------------- K0: expand relative-position bias ----------------
__global__ void k_bias_pre(const float* __restrict__ bt, const int* __restrict__ ri) {
    int h = blockIdx.x;  // 0..15
    for (int nm = threadIdx.x; nm < 4096; nm += blockDim.x)
        g_bias[h * 4096 + nm] = bt[ri[nm] * 16 + h];
}

// ---------------- K1/K3: tiled tf32 GEMM (NT), 256x128x32, 256 thr ----------------
// 8 warps x 64x64 warp tile. cp.async double-buffered smem (operands already
// tf32-rounded in gmem) + fragment double-buffering in the ks loop so
// crossbar (LDS) and tensor (MMA) overlap instead of alternating.
template <bool IS_QKV>
__global__ __launch_bounds__(256, 1) void k_gemm(const float* __restrict__ bias,
                                                 float* __restrict__ outp) {
    extern __shared__ float smem[];  // 2 buffers: A 256*36 + B 128*36 each

    const float* Asrc = IS_QKV ? (const float*)g_x : (const float*)g_att;
    const float* Wsrc = IS_QKV ? (const float*)g_wq : (const float*)g_wp;

    const int Cb   = blockIdx.x * 128;  // column tile (fast axis, A stays in L2)
    const int Rb   = blockIdx.y * 256;  // row tile
    const int tid  = threadIdx.x;
    const int lane = tid & 31, wid = tid >> 5;
    const int g = lane >> 2, t = lane & 3;
    const int wm = wid & 3, wn = wid >> 2;
    const int m0 = wm * 64, n0 = wn * 64;

    // copy descriptors: A 2048 16B chunks (8/thr), B 1024 (4/thr)
    const int lrow = tid >> 3, lc = (tid & 7) * 4;
    const uint32_t sbase   = smem_u32(smem);
    const uint32_t soff0   = (uint32_t)(lrow * 36 + lc) * 4u;  // bytes

    int aoff[8];
#pragma unroll
    for (int i = 0; i < 8; i++) {
        int row = lrow + i * 32;
        int src = IS_QKV ? permute_row(Rb + row) : (Rb + row);
        aoff[i] = src * 512 + lc;
    }
    int boff0 = (Cb + lrow) * 512 + lc;

    // issue one K-tile's copies into buffer j
    auto issue = [&](int j, int k0) {
        const uint32_t ab = sbase + (uint32_t)j * 55296u + soff0;
#pragma unroll
        for (int i = 0; i < 8; i++)
            CP_ASYNC16(ab + i * 4608u, Asrc + aoff[i] + k0);
        const uint32_t bb = ab + 36864u;
#pragma unroll
        for (int i = 0; i < 4; i++)
            CP_ASYNC16(bb + i * 4608u, Wsrc + boff0 + i * 16384 + k0);
        CP_COMMIT();
    };

    issue(0, 0);  // prologue

    float acc[4][8][4];
#pragma unroll
    for (int a = 0; a < 4; a++)
#pragma unroll
        for (int b = 0; b < 8; b++)
#pragma unroll
            for (int cc = 0; cc < 4; cc++) acc[a][b][cc] = 0.f;

    uint32_t fa[2][16], fb[2][16];

#pragma unroll 1
    for (int kt = 0; kt < 16; kt++) {
        CP_WAIT0();
        __syncthreads();  // buf[kt&1] ready; all warps done with prior MMAs
        if (kt < 15) issue((kt + 1) & 1, (kt + 1) * 32);

        const uint32_t* A = (const uint32_t*)(smem + (kt & 1) * 13824);
        const uint32_t* B = A + 9216;

        // load frags for ks=0
#pragma unroll
        for (int mf = 0; mf < 4; mf++) {
            int base = (m0 + mf * 16 + g) * 36 + t;
            fa[0][mf * 4 + 0] = A[base];
            fa[0][mf * 4 + 1] = A[base + 288];
            fa[0][mf * 4 + 2] = A[base + 4];
            fa[0][mf * 4 + 3] = A[base + 292];
        }
#pragma unroll
        for (int nf = 0; nf < 8; nf++) {
            int nb = (n0 + nf * 8 + g) * 36 + t;
            fb[0][nf * 2 + 0] = B[nb];
            fb[0][nf * 2 + 1] = B[nb + 4];
        }

#pragma unroll
        for (int ks = 0; ks < 4; ks++) {
            const int cur = ks & 1;
            if (ks < 3) {  // prefetch frags ks+1 (overlaps MMAs below)
                const int nxt = cur ^ 1;
                const int kk  = (ks + 1) * 8 + t;
#pragma unroll
                for (int mf = 0; mf < 4; mf++) {
                    int base = (m0 + mf * 16 + g) * 36 + kk;
                    fa[nxt][mf * 4 + 0] = A[base];
                    fa[nxt][mf * 4 + 1] = A[base + 288];
                    fa[nxt][mf * 4 + 2] = A[base + 4];
                    fa[nxt][mf * 4 + 3] = A[base + 292];
                }
#pragma unroll
                for (int nf = 0; nf < 8; nf++) {
                    int nb = (n0 + nf * 8 + g) * 36 + kk;
                    fb[nxt][nf * 2 + 0] = B[nb];
                    fb[nxt][nf * 2 + 1] = B[nb + 4];
                }
            }
#pragma unroll
            for (int nf = 0; nf < 8; nf++) {
                uint32_t b0 = fb[cur][nf * 2], b1 = fb[cur][nf * 2 + 1];
#pragma unroll
                for (int mf = 0; mf < 4; mf++)
                    MMA8(acc[mf][nf], fa[cur][mf * 4 + 0], fa[cur][mf * 4 + 1],
                         fa[cur][mf * 4 + 2], fa[cur][mf * 4 + 3], b0, b1);
            }
        }
    }

    // epilogue: stage four 128x64 quarters through smem for coalesced writes.
    // st = buf0 A region: last read in iter 14; all warps passed iter 15's sync.
    float* st = smem;  // 128*65 = 8320 floats < 9216
#pragma unroll 1
    for (int q = 0; q < 4; q++) {
        const int rh = q >> 1, ch = q & 1;
        if ((wm >> 1) == rh && wn == ch) {
            const int rbase = (wm & 1) * 64;
#pragma unroll
            for (int mf = 0; mf < 4; mf++)
#pragma unroll
                for (int nf = 0; nf < 8; nf++) {
                    int row = rbase + mf * 16 + g;
                    int col = nf * 8 + 2 * t;
                    st[row * 65 + col]           = acc[mf][nf][0];
                    st[row * 65 + col + 1]       = acc[mf][nf][1];
                    st[(row + 8) * 65 + col]     = acc[mf][nf][2];
                    st[(row + 8) * 65 + col + 1] = acc[mf][nf][3];
                }
        }
        __syncthreads();

        const int Ro = Rb + rh * 128;
        const int Co = Cb + ch * 64;
        if (IS_QKV) {
            const int s = Co >> 9;  // 0=q 1=k 2=v (uniform: Co is 64-aligned)
            float* buf  = (s == 0) ? g_q : (s == 1) ? g_k : g_v;
#pragma unroll
            for (int i = 0; i < 32; i++) {
                int idx = tid + i * 256;
                int m = idx >> 6, j = idx & 63;
                int r = Ro + m, o = Co + j;
                int hh = (o >> 5) & 15, d = o & 31;
                int wnd = r >> 6, n = r & 63;
                buf[((size_t)((wnd * 16 + hh) * 64 + n)) * 32 + d] = st[m * 65 + j] + bias[o];
            }
        } else {
#pragma unroll
            for (int i = 0; i < 32; i++) {
                int idx = tid + i * 256;
                int m = idx >> 6, j = idx & 63;
                int r = Ro + m, o = Co + j;
                int dst = permute_row(r);
                outp[(size_t)dst * 512 + o] = st[m * 65 + j] + bias[o];
            }
        }
        __syncthreads();
    }
}

// ---------------- K2: attention, one block per (window, head) ----------------
__global__ __launch_bounds__(128) void k_attn() {
    __shared__ float qs[64 * 36];
    __shared__ float kt_s[64 * 36];
    __shared__ float vs[64 * 36];
    __shared__ float ps[64 * 68];
    __shared__ int sid[64];

    const int w   = blockIdx.x;
    const int h   = blockIdx.y;
    const int tid = threadIdx.x;
    const int lane = tid & 31, wid = tid >> 5;
    const int g = lane >> 2, t = lane & 3;

    const size_t base = (size_t)(w * 16 + h) * 2048;
    const float scale = 0.17677669529663687f;

#pragma unroll
    for (int i = 0; i < 4; i++) {
        int ch  = tid + i * 128;
        int row = ch >> 3, c = ch & 7;
        int go = row * 32 + c * 4;
        int so = row * 36 + c * 4;
        float4 q4 = *(const float4*)(g_q + base + go);
        qs[so] = to_tf32(q4.x * scale); qs[so + 1] = to_tf32(q4.y * scale);
        qs[so + 2] = to_tf32(q4.z * scale); qs[so + 3] = to_tf32(q4.w * scale);
        float4 k4 = *(const float4*)(g_k + base + go);
        kt_s[so] = to_tf32(k4.x); kt_s[so + 1] = to_tf32(k4.y);
        kt_s[so + 2] = to_tf32(k4.z); kt_s[so + 3] = to_tf32(k4.w);
        float4 v4 = *(const float4*)(g_v + base + go);
        vs[so] = to_tf32(v4.x); vs[so + 1] = to_tf32(v4.y);
        vs[so + 2] = to_tf32(v4.z); vs[so + 3] = to_tf32(v4.w);
    }
    if (tid < 64) {
        int wIdx = w & 63;
        int hs = ((wIdx >> 3) << 3) | (tid >> 3);
        int ws = ((wIdx & 7) << 3) | (tid & 7);
        int rh = (hs < 56) ? 0 : (hs < 60 ? 1 : 2);
        int rw = (ws < 56) ? 0 : (ws < 60 ? 1 : 2);
        sid[tid] = rh * 3 + rw;
    }
    __syncthreads();

    const int m0 = wid * 16;
    float acc[8][4];
#pragma unroll
    for (int a = 0; a < 8; a++)
#pragma unroll
        for (int b = 0; b < 4; b++) acc[a][b] = 0.f;

    const uint32_t* Q = (const uint32_t*)qs;
    const uint32_t* K = (const uint32_t*)kt_s;
#pragma unroll
    for (int ks = 0; ks < 4; ks++) {
        const int kk = ks * 8 + t;
        int ab = (m0 + g) * 36 + kk;
        uint32_t a0 = Q[ab], a1 = Q[ab + 8 * 36], a2 = Q[ab + 4], a3 = Q[ab + 8 * 36 + 4];
#pragma unroll
        for (int nf = 0; nf < 8; nf++) {
            int nb = (nf * 8 + g) * 36 + kk;
            MMA8(acc[nf], a0, a1, a2, a3, K[nb], K[nb + 4]);
        }
    }

    const float* bh = g_bias + h * 4096;
    const int r0 = m0 + g, r1 = r0 + 8;
    const int id0 = sid[r0], id1 = sid[r1];
    float mx0 = -1e30f, mx1 = -1e30f;
#pragma unroll
    for (int nf = 0; nf < 8; nf++) {
        int c0 = nf * 8 + 2 * t;
        int ic0 = sid[c0], ic1 = sid[c0 + 1];
        acc[nf][0] += bh[r0 * 64 + c0]     + (id0 != ic0 ? -100.f : 0.f);
        acc[nf][1] += bh[r0 * 64 + c0 + 1] + (id0 != ic1 ? -100.f : 0.f);
        acc[nf][2] += bh[r1 * 64 + c0]     + (id1 != ic0 ? -100.f : 0.f);
        acc[nf][3] += bh[r1 * 64 + c0 + 1] + (id1 != ic1 ? -100.f : 0.f);
        mx0 = fmaxf(mx0, fmaxf(acc[nf][0], acc[nf][1]));
        mx1 = fmaxf(mx1, fmaxf(acc[nf][2], acc[nf][3]));
    }
    mx0 = fmaxf(mx0, __shfl_xor_sync(0xffffffffu, mx0, 1));
    mx0 = fmaxf(mx0, __shfl_xor_sync(0xffffffffu, mx0, 2));
    mx1 = fmaxf(mx1, __shfl_xor_sync(0xffffffffu, mx1, 1));
    mx1 = fmaxf(mx1, __shfl_xor_sync(0xffffffffu, mx1, 2));
    float s0 = 0.f, s1 = 0.f;
#pragma unroll
    for (int nf = 0; nf < 8; nf++) {
        acc[nf][0] = __expf(acc[nf][0] - mx0); s0 += acc[nf][0];
        acc[nf][1] = __expf(acc[nf][1] - mx0); s0 += acc[nf][1];
        acc[nf][2] = __expf(acc[nf][2] - mx1); s1 += acc[nf][2];
        acc[nf][3] = __expf(acc[nf][3] - mx1); s1 += acc[nf][3];
    }
    s0 += __shfl_xor_sync(0xffffffffu, s0, 1);
    s0 += __shfl_xor_sync(0xffffffffu, s0, 2);
    s1 += __shfl_xor_sync(0xffffffffu, s1, 1);
    s1 += __shfl_xor_sync(0xffffffffu, s1, 2);
    const float inv0 = 1.f / s0, inv1 = 1.f / s1;
#pragma unroll
    for (int nf = 0; nf < 8; nf++) {
        int c0 = nf * 8 + 2 * t;
        ps[r0 * 68 + c0]     = to_tf32(acc[nf][0] * inv0);
        ps[r0 * 68 + c0 + 1] = to_tf32(acc[nf][1] * inv0);
        ps[r1 * 68 + c0]     = to_tf32(acc[nf][2] * inv1);
        ps[r1 * 68 + c0 + 1] = to_tf32(acc[nf][3] * inv1);
    }
    __syncthreads();

    float acc2[4][4];
#pragma unroll
    for (int a = 0; a < 4; a++)
#pragma unroll
        for (int b = 0; b < 4; b++) acc2[a][b] = 0.f;
    const uint32_t* P = (const uint32_t*)ps;
    const uint32_t* V = (const uint32_t*)vs;
#pragma unroll
    for (int ks = 0; ks < 8; ks++) {
        const int kk = ks * 8 + t;
        int ab = (m0 + g) * 68 + kk;
        uint32_t a0 = P[ab], a1 = P[ab + 8 * 68], a2 = P[ab + 4], a3 = P[ab + 8 * 68 + 4];
#pragma unroll
        for (int nf = 0; nf < 4; nf++) {
            int nn = nf * 8 + g;
            MMA8(acc2[nf], a0, a1, a2, a3, V[kk * 36 + nn], V[(kk + 4) * 36 + nn]);
        }
    }

    // stage O (tf32-rounded for proj's cp.async path) then coalesced store
    float* ost = qs;
#pragma unroll
    for (int nf = 0; nf < 4; nf++) {
        int c0 = nf * 8 + 2 * t;
        ost[r0 * 36 + c0]     = to_tf32(acc2[nf][0]);
        ost[r0 * 36 + c0 + 1] = to_tf32(acc2[nf][1]);
        ost[r1 * 36 + c0]     = to_tf32(acc2[nf][2]);
        ost[r1 * 36 + c0 + 1] = to_tf32(acc2[nf][3]);
    }
    __syncthreads();
    const size_t ob = (size_t)(w * 64) * 512 + h * 32;
#pragma unroll
    for (int i = 0; i < 16; i++) {
        int idx = tid + i * 128;
        int row = idx >> 5, d = idx & 31;
        g_att[ob + (size_t)row * 512 + d] = ost[row * 36 + d];
    }
}

// ---------------- launch ----------------
static constexpr int SMEM_GEMM_BYTES = 2 * 13824 * 4;  // 110592

extern "C" void kernel_launch(void* const* d_in, const int* in_sizes, int n_in,
                              void* d_out, int out_size) {
    const float* x  = nullptr;  // 33554432
    const float* qw = nullptr;  // 786432
    const float* qb = nullptr;  // 1536
    const float* pw = nullptr;  // 262144
    const float* pb = nullptr;  // 512
    const float* bt = nullptr;  // 3600
    const int*   ri = nullptr;  // 4096
    for (int i = 0; i < n_in; i++) {
        switch (in_sizes[i]) {
            case 33554432: x  = (const float*)d_in[i]; break;
            case 786432:   qw = (const float*)d_in[i]; break;
            case 1536:     qb = (const float*)d_in[i]; break;
            case 262144:   pw = (const float*)d_in[i]; break;
            case 512:      pb = (const float*)d_in[i]; break;
            case 3600:     bt = (const float*)d_in[i]; break;
            case 4096:     ri = (const int*)d_in[i];   break;
            default: break;
        }
    }
    float* out = (float*)d_out;

    cudaFuncSetAttribute(k_gemm<true>, cudaFuncAttributeMaxDynamicSharedMemorySize,
                         SMEM_GEMM_BYTES);
    cudaFuncSetAttribute(k_gemm<false>, cudaFuncAttributeMaxDynamicSharedMemorySize,
                         SMEM_GEMM_BYTES);

    k_pre<<<8448, 1024>>>(x, qw, pw);
    k_bias_pre<<<16, 256>>>(bt, ri);
    k_gemm<true><<<dim3(12, 256), 256, SMEM_GEMM_BYTES>>>(qb, nullptr);
    k_attn<<<dim3(1024, 16), 128>>>();
    k_gemm<false><<<dim3(4, 256), 256, SMEM_GEMM_BYTES>>>(pb, out);
}

// round 10
// speedup vs baseline: 1.0966x; 1.0966x over previous
#include <cuda_runtime.h>
#include <cstdint>

// ---------------- problem constants ----------------
// B=16, H=W=64, C=512, NH=16, hd=32, WS=8, N=64, SS=4

// ---------------- device scratch ----------------
__device__ float g_q[1024 * 16 * 64 * 32];
__device__ float g_k[1024 * 16 * 64 * 32];
__device__ float g_v[1024 * 16 * 64 * 32];
__device__ float g_att[65536 * 512];
__device__ float g_bias[16 * 64 * 64];

// ---------------- helpers ----------------
__device__ __forceinline__ float to_tf32(float x) {
    float r;
    asm("cvt.rna.tf32.f32 %0, %1;" : "=f"(r) : "f"(x));
    return r;
}

__device__ __forceinline__ uint32_t smem_u32(const void* p) {
    uint32_t r;
    asm("{ .reg .u64 t; cvta.to.shared.u64 t, %1; cvt.u32.u64 %0, t; }"
        : "=r"(r) : "l"(p));
    return r;
}

#define MMA8(c, a0, a1, a2, a3, b0, b1)                                      \
    asm volatile(                                                            \
        "mma.sync.aligned.m16n8k8.row.col.f32.tf32.tf32.f32 "                \
        "{%0,%1,%2,%3}, {%4,%5,%6,%7}, {%8,%9}, {%0,%1,%2,%3};\n"            \
        : "+f"((c)[0]), "+f"((c)[1]), "+f"((c)[2]), "+f"((c)[3])             \
        : "r"(a0), "r"(a1), "r"(a2), "r"(a3), "r"(b0), "r"(b1))

#define CP_ASYNC16(dst_u32, src_ptr)                                         \
    asm volatile("cp.async.cg.shared.global [%0], [%1], 16;" ::              \
                 "r"(dst_u32), "l"(src_ptr))
#define CP_COMMIT() asm volatile("cp.async.commit_group;")
#define CP_WAIT0()  asm volatile("cp.async.wait_group 0;")

// window-token row -> original image row (shift + window partition fused).
__device__ __forceinline__ int permute_row(int r) {
    int b   = r >> 12;
    int rem = r & 4095;
    int wi  = rem >> 6, n = rem & 63;
    int hs  = ((wi >> 3) << 3) | (n >> 3);
    int ws  = ((wi & 7) << 3) | (n & 7);
    int hp  = (hs + 4) & 63;
    int wp  = (ws + 4) & 63;
    return (b << 12) | (hp << 6) | wp;
}

// ---------------- K0: expand relative-position bias ----------------
__global__ void k_bias_pre(const float* __restrict__ bt, const int* __restrict__ ri) {
    int h = blockIdx.x;  // 0..15
    for (int nm = threadIdx.x; nm < 4096; nm += blockDim.x)
        g_bias[h * 4096 + nm] = bt[ri[nm] * 16 + h];
}

// ---------------- K1/K3: tiled tf32 GEMM (NT), 256x128x32, 256 thr ----------------
// R6 configuration (best measured): single-buffered smem, register prefetch.
// QKV epilogue pre-rounds outputs to tf32 so k_attn can stage via cp.async.
template <bool IS_QKV>
__global__ __launch_bounds__(256, 1) void k_gemm(const float* __restrict__ Aglob,
                                                 const float* __restrict__ Wglob,
                                                 const float* __restrict__ bias,
                                                 float* __restrict__ outp) {
    extern __shared__ float smem[];        // 384*36 floats = 55296 B
    float* As = smem;                      // 256 * 36
    float* Bs = smem + 256 * 36;           // 128 * 36

    const float* Asrc = IS_QKV ? Aglob : (const float*)g_att;

    const int Cb   = blockIdx.x * 128;     // column tile (fast axis)
    const int Rb   = blockIdx.y * 256;     // row tile
    const int tid  = threadIdx.x;
    const int lane = tid & 31, wid = tid >> 5;
    const int g = lane >> 2, t = lane & 3;
    const int wm = wid & 3, wn = wid >> 2;
    const int m0 = wm * 64, n0 = wn * 64;

    const int lrow = tid >> 3, lc = (tid & 7) * 4;
    const int off0 = lrow * 36 + lc;

    int aoffg[8];
#pragma unroll
    for (int i = 0; i < 8; i++) {
        int row = lrow + i * 32;
        int src = IS_QKV ? permute_row(Rb + row) : (Rb + row);
        aoffg[i] = src * 512 + lc;
    }
    const float* bbase = Wglob + (size_t)(Cb + lrow) * 512 + lc;

    float4 ra[8], rb[4];
#pragma unroll
    for (int i = 0; i < 8; i++) ra[i] = *(const float4*)(Asrc + (size_t)aoffg[i]);
#pragma unroll
    for (int i = 0; i < 4; i++) rb[i] = *(const float4*)(bbase + (size_t)i * 32 * 512);

    float acc[4][8][4];
#pragma unroll
    for (int a = 0; a < 4; a++)
#pragma unroll
        for (int b = 0; b < 8; b++)
#pragma unroll
            for (int cc = 0; cc < 4; cc++) acc[a][b][cc] = 0.f;

#pragma unroll 1
    for (int kt = 0; kt < 16; kt++) {
#pragma unroll
        for (int i = 0; i < 8; i++) {
            float* d = As + off0 + i * 32 * 36;
            d[0] = to_tf32(ra[i].x); d[1] = to_tf32(ra[i].y);
            d[2] = to_tf32(ra[i].z); d[3] = to_tf32(ra[i].w);
        }
#pragma unroll
        for (int i = 0; i < 4; i++) {
            float* d = Bs + off0 + i * 32 * 36;
            d[0] = to_tf32(rb[i].x); d[1] = to_tf32(rb[i].y);
            d[2] = to_tf32(rb[i].z); d[3] = to_tf32(rb[i].w);
        }
        __syncthreads();

        if (kt < 15) {
            const int k0 = (kt + 1) * 32;
#pragma unroll
            for (int i = 0; i < 8; i++)
                ra[i] = *(const float4*)(Asrc + (size_t)aoffg[i] + k0);
#pragma unroll
            for (int i = 0; i < 4; i++)
                rb[i] = *(const float4*)(bbase + (size_t)i * 32 * 512 + k0);
        }

        const uint32_t* A = (const uint32_t*)As;
        const uint32_t* B = (const uint32_t*)Bs;
#pragma unroll
        for (int ks = 0; ks < 4; ks++) {
            const int kk = ks * 8 + t;
            uint32_t a[4][4];
#pragma unroll
            for (int mf = 0; mf < 4; mf++) {
                int base = (m0 + mf * 16 + g) * 36 + kk;
                a[mf][0] = A[base];
                a[mf][1] = A[base + 8 * 36];
                a[mf][2] = A[base + 4];
                a[mf][3] = A[base + 8 * 36 + 4];
            }
#pragma unroll
            for (int nf = 0; nf < 8; nf++) {
                int nb      = (n0 + nf * 8 + g) * 36 + kk;
                uint32_t b0 = B[nb], b1 = B[nb + 4];
#pragma unroll
                for (int mf = 0; mf < 4; mf++)
                    MMA8(acc[mf][nf], a[mf][0], a[mf][1], a[mf][2], a[mf][3], b0, b1);
            }
        }
        __syncthreads();
    }

    // epilogue: four 128x64 quarters staged through smem
    float* st = smem;  // 128*65 = 8320 floats
#pragma unroll 1
    for (int q = 0; q < 4; q++) {
        const int rh = q >> 1, ch = q & 1;
        if ((wm >> 1) == rh && wn == ch) {
            const int rbase = (wm & 1) * 64;
#pragma unroll
            for (int mf = 0; mf < 4; mf++)
#pragma unroll
                for (int nf = 0; nf < 8; nf++) {
                    int row = rbase + mf * 16 + g;
                    int col = nf * 8 + 2 * t;
                    st[row * 65 + col]           = acc[mf][nf][0];
                    st[row * 65 + col + 1]       = acc[mf][nf][1];
                    st[(row + 8) * 65 + col]     = acc[mf][nf][2];
                    st[(row + 8) * 65 + col + 1] = acc[mf][nf][3];
                }
        }
        __syncthreads();

        const int Ro = Rb + rh * 128;
        const int Co = Cb + ch * 64;
        if (IS_QKV) {
            const int s = Co >> 9;
            float* buf  = (s == 0) ? g_q : (s == 1) ? g_k : g_v;
#pragma unroll
            for (int i = 0; i < 32; i++) {
                int idx = tid + i * 256;
                int m = idx >> 6, j = idx & 63;
                int r = Ro + m, o = Co + j;
                int hh = (o >> 5) & 15, d = o & 31;
                int wnd = r >> 6, n = r & 63;
                // pre-rounded tf32 so k_attn can cp.async straight to MMA smem
                buf[((size_t)((wnd * 16 + hh) * 64 + n)) * 32 + d] =
                    to_tf32(st[m * 65 + j] + bias[o]);
            }
        } else {
#pragma unroll
            for (int i = 0; i < 32; i++) {
                int idx = tid + i * 256;
                int m = idx >> 6, j = idx & 63;
                int r = Ro + m, o = Co + j;
                int dst = permute_row(r);
                outp[(size_t)dst * 512 + o] = st[m * 65 + j] + bias[o];
            }
        }
        __syncthreads();
    }
}

// ---------------- K2: attention, one block per (window, head) ----------------
// v2: cp.async staging (inputs pre-rounded tf32), scale folded post-MMA,
// P kept in registers via k-permutation (no ps buffer / no restaging).
__global__ __launch_bounds__(128) void k_attn() {
    __shared__ float qs[64 * 36];
    __shared__ float ks_[64 * 36];
    __shared__ float vs[64 * 36];
    __shared__ int sid[64];

    const int w   = blockIdx.x;
    const int h   = blockIdx.y;
    const int tid = threadIdx.x;
    const int lane = tid & 31, wid = tid >> 5;
    const int g = lane >> 2, t = lane & 3;

    const size_t base = (size_t)(w * 16 + h) * 2048;
    const float scale = 0.17677669529663687f;  // 32^-0.5

    const uint32_t qb = smem_u32(qs), kb = smem_u32(ks_), vb = smem_u32(vs);
#pragma unroll
    for (int i = 0; i < 4; i++) {
        int ch  = tid + i * 128;
        int row = ch >> 3, c = ch & 7;
        uint32_t so = (uint32_t)(row * 36 + c * 4) * 4u;
        const size_t go = base + row * 32 + c * 4;
        CP_ASYNC16(qb + so, g_q + go);
        CP_ASYNC16(kb + so, g_k + go);
        CP_ASYNC16(vb + so, g_v + go);
    }
    CP_COMMIT();
    if (tid < 64) {
        int wIdx = w & 63;
        int hs = ((wIdx >> 3) << 3) | (tid >> 3);
        int ws = ((wIdx & 7) << 3) | (tid & 7);
        int rh = (hs < 56) ? 0 : (hs < 60 ? 1 : 2);
        int rw = (ws < 56) ? 0 : (ws < 60 ? 1 : 2);
        sid[tid] = rh * 3 + rw;
    }
    CP_WAIT0();
    __syncthreads();

    // S = q @ k^T (unscaled; scale applied below)
    const int m0 = wid * 16;
    float acc[8][4];
#pragma unroll
    for (int a = 0; a < 8; a++)
#pragma unroll
        for (int b = 0; b < 4; b++) acc[a][b] = 0.f;

    const uint32_t* Q = (const uint32_t*)qs;
    const uint32_t* K = (const uint32_t*)ks_;
#pragma unroll
    for (int ks = 0; ks < 4; ks++) {
        const int kk = ks * 8 + t;
        int ab = (m0 + g) * 36 + kk;
        uint32_t a0 = Q[ab], a1 = Q[ab + 288], a2 = Q[ab + 4], a3 = Q[ab + 292];
#pragma unroll
        for (int nf = 0; nf < 8; nf++) {
            int nb = (nf * 8 + g) * 36 + kk;
            MMA8(acc[nf], a0, a1, a2, a3, K[nb], K[nb + 4]);
        }
    }

    // scale + rel-pos bias + shift mask, softmax over rows r0/r1
    const float* bh = g_bias + h * 4096;
    const int r0 = m0 + g, r1 = r0 + 8;
    const int id0 = sid[r0], id1 = sid[r1];
    float mx0 = -1e30f, mx1 = -1e30f;
#pragma unroll
    for (int nf = 0; nf < 8; nf++) {
        int c0 = nf * 8 + 2 * t;
        int ic0 = sid[c0], ic1 = sid[c0 + 1];
        acc[nf][0] = fmaf(acc[nf][0], scale, bh[r0 * 64 + c0])     + (id0 != ic0 ? -100.f : 0.f);
        acc[nf][1] = fmaf(acc[nf][1], scale, bh[r0 * 64 + c0 + 1]) + (id0 != ic1 ? -100.f : 0.f);
        acc[nf][2] = fmaf(acc[nf][2], scale, bh[r1 * 64 + c0])     + (id1 != ic0 ? -100.f : 0.f);
        acc[nf][3] = fmaf(acc[nf][3], scale, bh[r1 * 64 + c0 + 1]) + (id1 != ic1 ? -100.f : 0.f);
        mx0 = fmaxf(mx0, fmaxf(acc[nf][0], acc[nf][1]));
        mx1 = fmaxf(mx1, fmaxf(acc[nf][2], acc[nf][3]));
    }
    mx0 = fmaxf(mx0, __shfl_xor_sync(0xffffffffu, mx0, 1));
    mx0 = fmaxf(mx0, __shfl_xor_sync(0xffffffffu, mx0, 2));
    mx1 = fmaxf(mx1, __shfl_xor_sync(0xffffffffu, mx1, 1));
    mx1 = fmaxf(mx1, __shfl_xor_sync(0xffffffffu, mx1, 2));
    float s0 = 0.f, s1 = 0.f;
#pragma unroll
    for (int nf = 0; nf < 8; nf++) {
        acc[nf][0] = __expf(acc[nf][0] - mx0); s0 += acc[nf][0];
        acc[nf][1] = __expf(acc[nf][1] - mx0); s0 += acc[nf][1];
        acc[nf][2] = __expf(acc[nf][2] - mx1); s1 += acc[nf][2];
        acc[nf][3] = __expf(acc[nf][3] - mx1); s1 += acc[nf][3];
    }
    s0 += __shfl_xor_sync(0xffffffffu, s0, 1);
    s0 += __shfl_xor_sync(0xffffffffu, s0, 2);
    s1 += __shfl_xor_sync(0xffffffffu, s1, 1);
    s1 += __shfl_xor_sync(0xffffffffu, s1, 2);
    const float inv0 = 1.f / s0, inv1 = 1.f / s1;
#pragma unroll
    for (int nf = 0; nf < 8; nf++) {
        acc[nf][0] = to_tf32(acc[nf][0] * inv0);
        acc[nf][1] = to_tf32(acc[nf][1] * inv0);
        acc[nf][2] = to_tf32(acc[nf][2] * inv1);
        acc[nf][3] = to_tf32(acc[nf][3] * inv1);
    }

    // O = P @ V with P straight from registers.
    // k-permutation trick: within each 8-token group, A-slot k-order is
    // (2t, 2t+1) (the C-fragment layout); feed V rows in the SAME order.
    float acc2[4][4];
#pragma unroll
    for (int a = 0; a < 4; a++)
#pragma unroll
        for (int b = 0; b < 4; b++) acc2[a][b] = 0.f;
    const uint32_t* V = (const uint32_t*)vs;
#pragma unroll
    for (int ks = 0; ks < 8; ks++) {
        uint32_t a0 = __float_as_uint(acc[ks][0]);  // (r0, 2t)
        uint32_t a1 = __float_as_uint(acc[ks][2]);  // (r1, 2t)
        uint32_t a2 = __float_as_uint(acc[ks][1]);  // (r0, 2t+1)
        uint32_t a3 = __float_as_uint(acc[ks][3]);  // (r1, 2t+1)
        const int k0 = ks * 8 + 2 * t;
#pragma unroll
        for (int nf = 0; nf < 4; nf++) {
            int nn = nf * 8 + g;
            MMA8(acc2[nf], a0, a1, a2, a3, V[k0 * 36 + nn], V[(k0 + 1) * 36 + nn]);
        }
    }

    __syncthreads();  // all warps done reading qs (Q) before reuse as staging
    float* ost = qs;
#pragma unroll
    for (int nf = 0; nf < 4; nf++) {
        int c0 = nf * 8 + 2 * t;
        ost[r0 * 36 + c0]     = acc2[nf][0];
        ost[r0 * 36 + c0 + 1] = acc2[nf][1];
        ost[r1 * 36 + c0]     = acc2[nf][2];
        ost[r1 * 36 + c0 + 1] = acc2[nf][3];
    }
    __syncthreads();
    const size_t ob = (size_t)(w * 64) * 512 + h * 32;
#pragma unroll
    for (int i = 0; i < 16; i++) {
        int idx = tid + i * 128;
        int row = idx >> 5, d = idx & 31;
        g_att[ob + (size_t)row * 512 + d] = ost[row * 36 + d];
    }
}

// ---------------- launch ----------------
static constexpr int SMEM_GEMM_BYTES = 384 * 36 * 4;  // 55296

extern "C" void kernel_launch(void* const* d_in, const int* in_sizes, int n_in,
                              void* d_out, int out_size) {
    const float* x  = nullptr;  // 33554432
    const float* qw = nullptr;  // 786432
    const float* qb = nullptr;  // 1536
    const float* pw = nullptr;  // 262144
    const float* pb = nullptr;  // 512
    const float* bt = nullptr;  // 3600
    const int*   ri = nullptr;  // 4096
    for (int i = 0; i < n_in; i++) {
        switch (in_sizes[i]) {
            case 33554432: x  = (const float*)d_in[i]; break;
            case 786432:   qw = (const float*)d_in[i]; break;
            case 1536:     qb = (const float*)d_in[i]; break;
            case 262144:   pw = (const float*)d_in[i]; break;
            case 512:      pb = (const float*)d_in[i]; break;
            case 3600:     bt = (const float*)d_in[i]; break;
            case 4096:     ri = (const int*)d_in[i];   break;
            default: break;
        }
    }
    float* out = (float*)d_out;

    cudaFuncSetAttribute(k_gemm<true>, cudaFuncAttributeMaxDynamicSharedMemorySize,
                         SMEM_GEMM_BYTES);
    cudaFuncSetAttribute(k_gemm<false>, cudaFuncAttributeMaxDynamicSharedMemorySize,
                         SMEM_GEMM_BYTES);

    k_bias_pre<<<16, 256>>>(bt, ri);
    k_gemm<true><<<dim3(12, 256), 256, SMEM_GEMM_BYTES>>>(x, qw, qb, nullptr);
    k_attn<<<dim3(1024, 16), 128>>>();
    k_gemm<false><<<dim3(4, 256), 256, SMEM_GEMM_BYTES>>>(nullptr, pw, pb, out);
}

// round 11
// speedup vs baseline: 1.4563x; 1.3280x over previous
#include <cuda_runtime.h>
#include <cuda_fp16.h>
#include <cstdint>

// ---------------- problem constants ----------------
// B=16, H=W=64, C=512, NH=16, hd=32, WS=8, N=64, SS=4

// ---------------- device scratch ----------------
__device__ __half g_qh[1024 * 16 * 64 * 32];   // [(w,h,n),d]
__device__ __half g_kh[1024 * 16 * 64 * 32];   // [(w,h,n),d]
__device__ __half g_vh[1024 * 16 * 64 * 32];   // [(w,h,d),n]  (transposed!)
__device__ float  g_att[65536 * 512];
__device__ float  g_bias[16 * 64 * 64];

// ---------------- helpers ----------------
__device__ __forceinline__ uint32_t pack2h(float lo, float hi) {
    uint32_t r;
    asm("cvt.rn.f16x2.f32 %0, %1, %2;" : "=r"(r) : "f"(hi), "f"(lo));
    return r;
}

__device__ __forceinline__ uint32_t smem_u32(const void* p) {
    uint32_t r;
    asm("{ .reg .u64 t; cvta.to.shared.u64 t, %1; cvt.u32.u64 %0, t; }"
        : "=r"(r) : "l"(p));
    return r;
}

// fp16 MMA, fp32 accumulate: D(16x8) += A(16x16) * B(16x8)
#define MMAH(c, a0, a1, a2, a3, b0, b1)                                      \
    asm volatile(                                                            \
        "mma.sync.aligned.m16n8k16.row.col.f32.f16.f16.f32 "                 \
        "{%0,%1,%2,%3}, {%4,%5,%6,%7}, {%8,%9}, {%0,%1,%2,%3};\n"            \
        : "+f"((c)[0]), "+f"((c)[1]), "+f"((c)[2]), "+f"((c)[3])             \
        : "r"(a0), "r"(a1), "r"(a2), "r"(a3), "r"(b0), "r"(b1))

#define CP_ASYNC16(dst_u32, src_ptr)                                         \
    asm volatile("cp.async.cg.shared.global [%0], [%1], 16;" ::              \
                 "r"(dst_u32), "l"(src_ptr))
#define CP_COMMIT() asm volatile("cp.async.commit_group;")
#define CP_WAIT0()  asm volatile("cp.async.wait_group 0;")

// window-token row -> original image row (shift + window partition fused).
__device__ __forceinline__ int permute_row(int r) {
    int b   = r >> 12;
    int rem = r & 4095;
    int wi  = rem >> 6, n = rem & 63;
    int hs  = ((wi >> 3) << 3) | (n >> 3);
    int ws  = ((wi & 7) << 3) | (n & 7);
    int hp  = (hs + 4) & 63;
    int wp  = (ws + 4) & 63;
    return (b << 12) | (hp << 6) | wp;
}

// ---------------- K0: expand relative-position bias ----------------
__global__ void k_bias_pre(const float* __restrict__ bt, const int* __restrict__ ri) {
    int h = blockIdx.x;  // 0..15
    for (int nm = threadIdx.x; nm < 4096; nm += blockDim.x)
        g_bias[h * 4096 + nm] = bt[ri[nm] * 16 + h];
}

// ---------------- K1/K3: fp16 GEMM (NT), 256x128x32, 256 thr ----------------
// 8 warps x 64x64 warp tile, m16n8k16 fp16 MMA (full tensor rate), fp32 accum.
// smem tiles: half2-packed, row stride 20 b32 (16 data + 4 pad, conflict-free).
// blockIdx.x = COLUMN tile (L2 reuse of A row tile); blockIdx.y = row tile.
template <bool IS_QKV>
__global__ __launch_bounds__(256, 1) void k_gemm(const float* __restrict__ Aglob,
                                                 const float* __restrict__ Wglob,
                                                 const float* __restrict__ bias,
                                                 float* __restrict__ outp) {
    __shared__ float smem[8320];           // C-staging needs 8320 f32; tiles use 7680 b32
    uint32_t* As = (uint32_t*)smem;        // 256 * 20 b32
    uint32_t* Bs = As + 5120;              // 128 * 20 b32

    const float* Asrc = IS_QKV ? Aglob : (const float*)g_att;

    const int Cb   = blockIdx.x * 128;     // column tile (fast axis)
    const int Rb   = blockIdx.y * 256;     // row tile
    const int tid  = threadIdx.x;
    const int lane = tid & 31, wid = tid >> 5;
    const int g = lane >> 2, t = lane & 3;
    const int wm = wid & 3, wn = wid >> 2;
    const int m0 = wm * 64, n0 = wn * 64;

    // gmem: each thread loads 4 consecutive fp32 (one float4) per row-chunk
    const int lrow = tid >> 3, lc = (tid & 7) * 4;
    const int off0 = lrow * 20 + (tid & 7) * 2;  // b32 offset for this thread's 2 b32

    int aoffg[8];
#pragma unroll
    for (int i = 0; i < 8; i++) {
        int row = lrow + i * 32;
        int src = IS_QKV ? permute_row(Rb + row) : (Rb + row);
        aoffg[i] = src * 512 + lc;
    }
    const float* bbase = Wglob + (size_t)(Cb + lrow) * 512 + lc;

    float4 ra[8], rb[4];
#pragma unroll
    for (int i = 0; i < 8; i++) ra[i] = *(const float4*)(Asrc + (size_t)aoffg[i]);
#pragma unroll
    for (int i = 0; i < 4; i++) rb[i] = *(const float4*)(bbase + (size_t)i * 32 * 512);

    float acc[4][8][4];
#pragma unroll
    for (int a = 0; a < 4; a++)
#pragma unroll
        for (int b = 0; b < 8; b++)
#pragma unroll
            for (int cc = 0; cc < 4; cc++) acc[a][b][cc] = 0.f;

#pragma unroll 1
    for (int kt = 0; kt < 16; kt++) {
        // cvt fp32 -> half2 and store (2 b32 per chunk)
#pragma unroll
        for (int i = 0; i < 8; i++) {
            uint32_t* d = As + off0 + i * 32 * 20;
            d[0] = pack2h(ra[i].x, ra[i].y);
            d[1] = pack2h(ra[i].z, ra[i].w);
        }
#pragma unroll
        for (int i = 0; i < 4; i++) {
            uint32_t* d = Bs + off0 + i * 32 * 20;
            d[0] = pack2h(rb[i].x, rb[i].y);
            d[1] = pack2h(rb[i].z, rb[i].w);
        }
        __syncthreads();

        if (kt < 15) {
            const int k0 = (kt + 1) * 32;
#pragma unroll
            for (int i = 0; i < 8; i++)
                ra[i] = *(const float4*)(Asrc + (size_t)aoffg[i] + k0);
#pragma unroll
            for (int i = 0; i < 4; i++)
                rb[i] = *(const float4*)(bbase + (size_t)i * 32 * 512 + k0);
        }

        // 2 k16-steps per 32-K tile
#pragma unroll
        for (int ks = 0; ks < 2; ks++) {
            const int kk = ks * 8 + t;
            uint32_t a[4][4];
#pragma unroll
            for (int mf = 0; mf < 4; mf++) {
                int base = (m0 + mf * 16 + g) * 20 + kk;
                a[mf][0] = As[base];            // (row g,   k 2t..2t+1)
                a[mf][1] = As[base + 160];      // (row g+8, k 2t..2t+1)
                a[mf][2] = As[base + 4];        // (row g,   k 8+2t..)
                a[mf][3] = As[base + 164];      // (row g+8, k 8+2t..)
            }
#pragma unroll
            for (int nf = 0; nf < 8; nf++) {
                int nb      = (n0 + nf * 8 + g) * 20 + kk;
                uint32_t b0 = Bs[nb], b1 = Bs[nb + 4];
#pragma unroll
                for (int mf = 0; mf < 4; mf++)
                    MMAH(acc[mf][nf], a[mf][0], a[mf][1], a[mf][2], a[mf][3], b0, b1);
            }
        }
        __syncthreads();
    }

    // epilogue: four 128x64 quarters staged through smem
    float* st = smem;  // 128*65 = 8320 floats
#pragma unroll 1
    for (int q = 0; q < 4; q++) {
        const int rh = q >> 1, ch = q & 1;
        if ((wm >> 1) == rh && wn == ch) {
            const int rbase = (wm & 1) * 64;
#pragma unroll
            for (int mf = 0; mf < 4; mf++)
#pragma unroll
                for (int nf = 0; nf < 8; nf++) {
                    int row = rbase + mf * 16 + g;
                    int col = nf * 8 + 2 * t;
                    st[row * 65 + col]           = acc[mf][nf][0];
                    st[row * 65 + col + 1]       = acc[mf][nf][1];
                    st[(row + 8) * 65 + col]     = acc[mf][nf][2];
                    st[(row + 8) * 65 + col + 1] = acc[mf][nf][3];
                }
        }
        __syncthreads();

        const int Ro = Rb + rh * 128;
        const int Co = Cb + ch * 64;
        if (IS_QKV) {
            const int s = Co >> 9;  // 0=q 1=k 2=v
            if (s < 2) {
                __half* buf = (s == 0) ? g_qh : g_kh;
                // half2 pairs: 4096 pairs per quarter
#pragma unroll
                for (int i = 0; i < 16; i++) {
                    int p  = tid + i * 256;
                    int m  = p >> 5, jj = (p & 31) * 2;
                    int r  = Ro + m, o = Co + jj;
                    int hh = (o >> 5) & 15, d = o & 31;   // d even
                    int wnd = r >> 6, n = r & 63;
                    float v0 = st[m * 65 + jj]     + bias[o];
                    float v1 = st[m * 65 + jj + 1] + bias[o + 1];
                    *(__half2*)&buf[((size_t)((wnd * 16 + hh) * 64 + n)) * 32 + d] =
                        __floats2half2_rn(v0, v1);
                }
            } else {
                // V: transposed layout [(w,h,d), n]; m-fast loop -> coalesced n
#pragma unroll
                for (int i = 0; i < 32; i++) {
                    int idx = tid + i * 256;
                    int m = idx & 127, jj = idx >> 7;
                    int r = Ro + m, o = Co + jj;
                    int hh = (o >> 5) & 15, d = o & 31;
                    int wnd = r >> 6, n = r & 63;
                    float v = st[m * 65 + jj] + bias[o];
                    g_vh[((size_t)((wnd * 16 + hh) * 32 + d)) * 64 + n] = __float2half(v);
                }
            }
        } else {
#pragma unroll
            for (int i = 0; i < 32; i++) {
                int idx = tid + i * 256;
                int m = idx >> 6, j = idx & 63;
                int r = Ro + m, o = Co + j;
                int dst = permute_row(r);
                outp[(size_t)dst * 512 + o] = st[m * 65 + j] + bias[o];
            }
        }
        __syncthreads();
    }
}

// ---------------- K2: attention (fp16 MMA), one block per (window, head) ----
__global__ __launch_bounds__(128) void k_attn() {
    // qs/ks: [64 tok][20 b32], vs_t: [32 d][36 b32]; ost reuses front as fp32
    __shared__ uint32_t sm[1280 + 1280 + 1152];
    __shared__ int sid[64];
    uint32_t* qs  = sm;
    uint32_t* kss = sm + 1280;
    uint32_t* vst = sm + 2560;

    const int w   = blockIdx.x;
    const int h   = blockIdx.y;
    const int tid = threadIdx.x;
    const int lane = tid & 31, wid = tid >> 5;
    const int g = lane >> 2, t = lane & 3;

    const size_t base = (size_t)(w * 16 + h) * 2048;   // halves
    const float scale = 0.17677669529663687f;          // 32^-0.5

    const uint32_t qb = smem_u32(qs), kb = smem_u32(kss), vb = smem_u32(vst);
    // q/k: 64 rows x 4 chunks (16B = 8 halves); v: 32 rows x 8 chunks
#pragma unroll
    for (int i = 0; i < 2; i++) {
        int c   = tid + i * 128;              // 0..255
        int row = c >> 2, cc = c & 3;
        uint32_t so = (uint32_t)(row * 20 + cc * 4) * 4u;
        CP_ASYNC16(qb + so, g_qh + base + row * 32 + cc * 8);
        CP_ASYNC16(kb + so, g_kh + base + row * 32 + cc * 8);
        int d = c >> 3, c2 = c & 7;
        CP_ASYNC16(vb + (uint32_t)(d * 36 + c2 * 4) * 4u, g_vh + base + d * 64 + c2 * 8);
    }
    CP_COMMIT();
    if (tid < 64) {
        int wIdx = w & 63;
        int hs = ((wIdx >> 3) << 3) | (tid >> 3);
        int ws = ((wIdx & 7) << 3) | (tid & 7);
        int rh = (hs < 56) ? 0 : (hs < 60 ? 1 : 2);
        int rw = (ws < 56) ? 0 : (ws < 60 ? 1 : 2);
        sid[tid] = rh * 3 + rw;
    }
    CP_WAIT0();
    __syncthreads();

    // S = q @ k^T  (hd=32 -> 2 k16 steps)
    const int m0 = wid * 16;
    float acc[8][4];
#pragma unroll
    for (int a = 0; a < 8; a++)
#pragma unroll
        for (int b = 0; b < 4; b++) acc[a][b] = 0.f;

#pragma unroll
    for (int ks = 0; ks < 2; ks++) {
        const int kk = ks * 8 + t;
        int ab = (m0 + g) * 20 + kk;
        uint32_t a0 = qs[ab], a1 = qs[ab + 160], a2 = qs[ab + 4], a3 = qs[ab + 164];
#pragma unroll
        for (int nf = 0; nf < 8; nf++) {
            int nb = (nf * 8 + g) * 20 + kk;
            MMAH(acc[nf], a0, a1, a2, a3, kss[nb], kss[nb + 4]);
        }
    }

    // scale + rel-pos bias + shift mask, softmax (rows r0/r1 per lane)
    const float* bh = g_bias + h * 4096;
    const int r0 = m0 + g, r1 = r0 + 8;
    const int id0 = sid[r0], id1 = sid[r1];
    float mx0 = -1e30f, mx1 = -1e30f;
#pragma unroll
    for (int nf = 0; nf < 8; nf++) {
        int c0 = nf * 8 + 2 * t;
        int ic0 = sid[c0], ic1 = sid[c0 + 1];
        acc[nf][0] = fmaf(acc[nf][0], scale, bh[r0 * 64 + c0])     + (id0 != ic0 ? -100.f : 0.f);
        acc[nf][1] = fmaf(acc[nf][1], scale, bh[r0 * 64 + c0 + 1]) + (id0 != ic1 ? -100.f : 0.f);
        acc[nf][2] = fmaf(acc[nf][2], scale, bh[r1 * 64 + c0])     + (id1 != ic0 ? -100.f : 0.f);
        acc[nf][3] = fmaf(acc[nf][3], scale, bh[r1 * 64 + c0 + 1]) + (id1 != ic1 ? -100.f : 0.f);
        mx0 = fmaxf(mx0, fmaxf(acc[nf][0], acc[nf][1]));
        mx1 = fmaxf(mx1, fmaxf(acc[nf][2], acc[nf][3]));
    }
    mx0 = fmaxf(mx0, __shfl_xor_sync(0xffffffffu, mx0, 1));
    mx0 = fmaxf(mx0, __shfl_xor_sync(0xffffffffu, mx0, 2));
    mx1 = fmaxf(mx1, __shfl_xor_sync(0xffffffffu, mx1, 1));
    mx1 = fmaxf(mx1, __shfl_xor_sync(0xffffffffu, mx1, 2));
    float s0 = 0.f, s1 = 0.f;
#pragma unroll
    for (int nf = 0; nf < 8; nf++) {
        acc[nf][0] = __expf(acc[nf][0] - mx0); s0 += acc[nf][0];
        acc[nf][1] = __expf(acc[nf][1] - mx0); s0 += acc[nf][1];
        acc[nf][2] = __expf(acc[nf][2] - mx1); s1 += acc[nf][2];
        acc[nf][3] = __expf(acc[nf][3] - mx1); s1 += acc[nf][3];
    }
    s0 += __shfl_xor_sync(0xffffffffu, s0, 1);
    s0 += __shfl_xor_sync(0xffffffffu, s0, 2);
    s1 += __shfl_xor_sync(0xffffffffu, s1, 1);
    s1 += __shfl_xor_sync(0xffffffffu, s1, 2);
    const float inv0 = 1.f / s0, inv1 = 1.f / s1;

    // O = P @ V: P packed from C-fragments into k16 A-operands (no smem trip).
    // k16 group j covers tokens 16j..16j+15: a0 = (r0, tok 16j+2t,+1) = acc[2j][0..1]
    float acc2[4][4];
#pragma unroll
    for (int a = 0; a < 4; a++)
#pragma unroll
        for (int b = 0; b < 4; b++) acc2[a][b] = 0.f;
#pragma unroll
    for (int j = 0; j < 4; j++) {
        uint32_t a0 = pack2h(acc[2 * j][0] * inv0,     acc[2 * j][1] * inv0);
        uint32_t a1 = pack2h(acc[2 * j][2] * inv1,     acc[2 * j][3] * inv1);
        uint32_t a2 = pack2h(acc[2 * j + 1][0] * inv0, acc[2 * j + 1][1] * inv0);
        uint32_t a3 = pack2h(acc[2 * j + 1][2] * inv1, acc[2 * j + 1][3] * inv1);
        const int kk = j * 8 + t;
#pragma unroll
        for (int nf = 0; nf < 4; nf++) {
            int nb = (nf * 8 + g) * 36 + kk;   // vs_t row = d, halves = tokens
            MMAH(acc2[nf], a0, a1, a2, a3, vst[nb], vst[nb + 4]);
        }
    }

    __syncthreads();  // everyone done reading qs/kss before reuse as staging
    float* ost = (float*)sm;  // 64 x 36 floats = 2304 <= 2560 b32
#pragma unroll
    for (int nf = 0; nf < 4; nf++) {
        int c0 = nf * 8 + 2 * t;
        ost[r0 * 36 + c0]     = acc2[nf][0];
        ost[r0 * 36 + c0 + 1] = acc2[nf][1];
        ost[r1 * 36 + c0]     = acc2[nf][2];
        ost[r1 * 36 + c0 + 1] = acc2[nf][3];
    }
    __syncthreads();
    const size_t ob = (size_t)(w * 64) * 512 + h * 32;
#pragma unroll
    for (int i = 0; i < 16; i++) {
        int idx = tid + i * 128;
        int row = idx >> 5, d = idx & 31;
        g_att[ob + (size_t)row * 512 + d] = ost[row * 36 + d];
    }
}

// ---------------- launch ----------------
extern "C" void kernel_launch(void* const* d_in, const int* in_sizes, int n_in,
                              void* d_out, int out_size) {
    const float* x  = nullptr;  // 33554432
    const float* qw = nullptr;  // 786432
    const float* qb = nullptr;  // 1536
    const float* pw = nullptr;  // 262144
    const float* pb = nullptr;  // 512
    const float* bt = nullptr;  // 3600
    const int*   ri = nullptr;  // 4096
    for (int i = 0; i < n_in; i++) {
        switch (in_sizes[i]) {
            case 33554432: x  = (const float*)d_in[i]; break;
            case 786432:   qw = (const float*)d_in[i]; break;
            case 1536:     qb = (const float*)d_in[i]; break;
            case 262144:   pw = (const float*)d_in[i]; break;
            case 512:      pb = (const float*)d_in[i]; break;
            case 3600:     bt = (const float*)d_in[i]; break;
            case 4096:     ri = (const int*)d_in[i];   break;
            default: break;
        }
    }
    float* out = (float*)d_out;

    k_bias_pre<<<16, 256>>>(bt, ri);
    k_gemm<true><<<dim3(12, 256), 256>>>(x, qw, qb, nullptr);
    k_attn<<<dim3(1024, 16), 128>>>();
    k_gemm<false><<<dim3(4, 256), 256>>>(nullptr, pw, pb, out);
}

// round 12
// speedup vs baseline: 1.6365x; 1.1238x over previous
#include <cuda_runtime.h>
#include <cuda_fp16.h>
#include <cstdint>

// ---------------- problem constants ----------------
// B=16, H=W=64, C=512, NH=16, hd=32, WS=8, N=64, SS=4

// ---------------- device scratch ----------------
__device__ __half g_xh[33554432];              // fp16 query (pre-rounded)
__device__ __half g_wqh[786432];               // fp16 qkv_w
__device__ __half g_wph[262144];               // fp16 proj_w
__device__ __half g_atth[33554432];            // fp16 attention output
__device__ __half g_qh[1024 * 16 * 64 * 32];   // [(w,h,n),d]
__device__ __half g_kh[1024 * 16 * 64 * 32];   // [(w,h,n),d]
__device__ __half g_vh[1024 * 16 * 64 * 32];   // [(w,h,d),n]  (transposed)
__device__ float  g_bias[16 * 64 * 64];

// ---------------- helpers ----------------
__device__ __forceinline__ uint32_t pack2h(float lo, float hi) {
    uint32_t r;
    asm("cvt.rn.f16x2.f32 %0, %1, %2;" : "=r"(r) : "f"(hi), "f"(lo));
    return r;
}

__device__ __forceinline__ uint32_t smem_u32(const void* p) {
    uint32_t r;
    asm("{ .reg .u64 t; cvta.to.shared.u64 t, %1; cvt.u32.u64 %0, t; }"
        : "=r"(r) : "l"(p));
    return r;
}

// fp16 MMA, fp32 accumulate: D(16x8) += A(16x16) * B(16x8)
#define MMAH(c, a0, a1, a2, a3, b0, b1)                                      \
    asm volatile(                                                            \
        "mma.sync.aligned.m16n8k16.row.col.f32.f16.f16.f32 "                 \
        "{%0,%1,%2,%3}, {%4,%5,%6,%7}, {%8,%9}, {%0,%1,%2,%3};\n"            \
        : "+f"((c)[0]), "+f"((c)[1]), "+f"((c)[2]), "+f"((c)[3])             \
        : "r"(a0), "r"(a1), "r"(a2), "r"(a3), "r"(b0), "r"(b1))

#define CP_ASYNC16(dst_u32, src_ptr)                                         \
    asm volatile("cp.async.cg.shared.global [%0], [%1], 16;" ::              \
                 "r"(dst_u32), "l"(src_ptr))
#define CP_COMMIT() asm volatile("cp.async.commit_group;")
#define CP_WAIT0()  asm volatile("cp.async.wait_group 0;")

// window-token row -> original image row (shift + window partition fused).
__device__ __forceinline__ int permute_row(int r) {
    int b   = r >> 12;
    int rem = r & 4095;
    int wi  = rem >> 6, n = rem & 63;
    int hs  = ((wi >> 3) << 3) | (n >> 3);
    int ws  = ((wi & 7) << 3) | (n & 7);
    int hp  = (hs + 4) & 63;
    int wp  = (ws + 4) & 63;
    return (b << 12) | (hp << 6) | wp;
}

// ---------------- K-1: pre-round x / qkv_w / proj_w to fp16 ----------------
__global__ __launch_bounds__(1024) void k_pre(const float* __restrict__ x,
                                              const float* __restrict__ qw,
                                              const float* __restrict__ pw) {
    int i = blockIdx.x * 1024 + threadIdx.x;  // float4 index, < 8650752
    float4 v;
    __half2* dst;
    if (i < 8388608) {
        v   = ((const float4*)x)[i];
        dst = (__half2*)g_xh + (size_t)i * 2;
    } else if (i < 8585216) {
        int j = i - 8388608;
        v   = ((const float4*)qw)[j];
        dst = (__half2*)g_wqh + (size_t)j * 2;
    } else {
        int j = i - 8585216;
        v   = ((const float4*)pw)[j];
        dst = (__half2*)g_wph + (size_t)j * 2;
    }
    dst[0] = __floats2half2_rn(v.x, v.y);
    dst[1] = __floats2half2_rn(v.z, v.w);
}

// ---------------- K0: expand relative-position bias ----------------
__global__ void k_bias_pre(const float* __restrict__ bt, const int* __restrict__ ri) {
    int h = blockIdx.x;  // 0..15
    for (int nm = threadIdx.x; nm < 4096; nm += blockDim.x)
        g_bias[h * 4096 + nm] = bt[ri[nm] * 16 + h];
}

// ---------------- K1/K3: fp16 GEMM (NT), 128x128x32, 128 thr -----------------
// 4 warps x 64x64 warp tile; cp.async double-buffer, ONE sync per K-tile.
// 2 CTAs/SM (128 thr, 40KB static smem) -> cross-CTA latency hiding.
// blockIdx.x = COLUMN tile (L2 reuse of A row tile); blockIdx.y = row tile.
template <bool IS_QKV>
__global__ __launch_bounds__(128, 2) void k_gemm(const float* __restrict__ bias,
                                                 float* __restrict__ outp) {
    __shared__ uint32_t sm[10240];   // 40960B: 2 buffers x (A 2560 + B 2560 b32)

    const __half* Asrc = IS_QKV ? g_xh : g_atth;
    const __half* Wsrc = IS_QKV ? g_wqh : g_wph;

    const int Cb   = blockIdx.x * 128;   // column tile (fast axis)
    const int Rb   = blockIdx.y * 128;   // row tile
    const int tid  = threadIdx.x;
    const int lane = tid & 31, wid = tid >> 5;
    const int g = lane >> 2, t = lane & 3;
    const int wm = wid & 1, wn = wid >> 1;
    const int m0 = wm * 64, n0 = wn * 64;

    // cp.async assignments: 512 chunks of 16B per matrix, 4/thread each.
    const int lrow4 = tid >> 2, cc4 = tid & 3;   // row-within-32, chunk-in-row
    const uint32_t sbase = smem_u32(sm);

    int asrc_off[4], bsrc_off[4];
    uint32_t dstoff[4];
#pragma unroll
    for (int i = 0; i < 4; i++) {
        int row = lrow4 + i * 32;
        int src = IS_QKV ? permute_row(Rb + row) : (Rb + row);
        asrc_off[i] = src * 512 + cc4 * 8;
        bsrc_off[i] = (Cb + row) * 512 + cc4 * 8;
        dstoff[i]   = (uint32_t)(row * 20 + cc4 * 4) * 4u;
    }

    auto issue = [&](int j, int k0) {
        const uint32_t ab = sbase + (uint32_t)j * 20480u;
        const uint32_t bb = ab + 10240u;
#pragma unroll
        for (int i = 0; i < 4; i++)
            CP_ASYNC16(ab + dstoff[i], Asrc + asrc_off[i] + k0);
#pragma unroll
        for (int i = 0; i < 4; i++)
            CP_ASYNC16(bb + dstoff[i], Wsrc + bsrc_off[i] + k0);
        CP_COMMIT();
    };

    issue(0, 0);

    float acc[4][8][4];
#pragma unroll
    for (int a = 0; a < 4; a++)
#pragma unroll
        for (int b = 0; b < 8; b++)
#pragma unroll
            for (int cc = 0; cc < 4; cc++) acc[a][b][cc] = 0.f;

#pragma unroll 1
    for (int kt = 0; kt < 16; kt++) {
        CP_WAIT0();          // tile kt landed (only outstanding group)
        __syncthreads();     // all warps past kt-1 MMAs; data visible
        if (kt < 15) issue((kt + 1) & 1, (kt + 1) * 32);

        const uint32_t* A = sm + (kt & 1) * 5120;
        const uint32_t* B = A + 2560;
#pragma unroll
        for (int ks = 0; ks < 2; ks++) {
            const int kk = ks * 8 + t;
            uint32_t a[4][4];
#pragma unroll
            for (int mf = 0; mf < 4; mf++) {
                int base = (m0 + mf * 16 + g) * 20 + kk;
                a[mf][0] = A[base];
                a[mf][1] = A[base + 160];
                a[mf][2] = A[base + 4];
                a[mf][3] = A[base + 164];
            }
#pragma unroll
            for (int nf = 0; nf < 8; nf++) {
                int nb      = (n0 + nf * 8 + g) * 20 + kk;
                uint32_t b0 = B[nb], b1 = B[nb + 4];
#pragma unroll
                for (int mf = 0; mf < 4; mf++)
                    MMAH(acc[mf][nf], a[mf][0], a[mf][1], a[mf][2], a[mf][3], b0, b1);
            }
        }
    }
    __syncthreads();  // everyone done with MMAs before smem reuse

    // epilogue: two 128x64 halves staged through smem
    float* st = (float*)sm;  // 128*65 = 8320 f32 <= 10240 b32
#pragma unroll 1
    for (int hh = 0; hh < 2; hh++) {
        if (wn == hh) {
#pragma unroll
            for (int mf = 0; mf < 4; mf++)
#pragma unroll
                for (int nf = 0; nf < 8; nf++) {
                    int row = m0 + mf * 16 + g;
                    int col = nf * 8 + 2 * t;
                    st[row * 65 + col]           = acc[mf][nf][0];
                    st[row * 65 + col + 1]       = acc[mf][nf][1];
                    st[(row + 8) * 65 + col]     = acc[mf][nf][2];
                    st[(row + 8) * 65 + col + 1] = acc[mf][nf][3];
                }
        }
        __syncthreads();

        const int Co = Cb + hh * 64;
        if (IS_QKV) {
            const int s = Co >> 9;  // 0=q 1=k 2=v (uniform)
            if (s < 2) {
                __half* buf = (s == 0) ? g_qh : g_kh;
#pragma unroll
                for (int i = 0; i < 32; i++) {
                    int p  = tid + i * 128;
                    int m  = p >> 5, jj = (p & 31) * 2;
                    int r  = Rb + m, o = Co + jj;
                    int hd = (o >> 5) & 15, d = o & 31;
                    int wnd = r >> 6, n = r & 63;
                    float v0 = st[m * 65 + jj]     + bias[o];
                    float v1 = st[m * 65 + jj + 1] + bias[o + 1];
                    *(__half2*)&buf[((size_t)((wnd * 16 + hd) * 64 + n)) * 32 + d] =
                        __floats2half2_rn(v0, v1);
                }
            } else {
                // V transposed: [(w,h,d), n]; m-fast -> coalesced n
#pragma unroll
                for (int i = 0; i < 64; i++) {
                    int idx = tid + i * 128;
                    int m = idx & 127, jj = idx >> 7;
                    int r = Rb + m, o = Co + jj;
                    int hd = (o >> 5) & 15, d = o & 31;
                    int wnd = r >> 6, n = r & 63;
                    float v = st[m * 65 + jj] + bias[o];
                    g_vh[((size_t)((wnd * 16 + hd) * 32 + d)) * 64 + n] = __float2half(v);
                }
            }
        } else {
#pragma unroll
            for (int i = 0; i < 64; i++) {
                int idx = tid + i * 128;
                int m = idx >> 6, j = idx & 63;
                int r = Rb + m, o = Co + j;
                int dst = permute_row(r);
                outp[(size_t)dst * 512 + o] = st[m * 65 + j] + bias[o];
            }
        }
        __syncthreads();
    }
}

// ---------------- K2: attention (fp16 MMA), one block per (window, head) ----
__global__ __launch_bounds__(128) void k_attn() {
    __shared__ uint32_t sm[1280 + 1280 + 1152];
    __shared__ int sid[64];
    uint32_t* qs  = sm;
    uint32_t* kss = sm + 1280;
    uint32_t* vst = sm + 2560;

    const int w   = blockIdx.x;
    const int h   = blockIdx.y;
    const int tid = threadIdx.x;
    const int lane = tid & 31, wid = tid >> 5;
    const int g = lane >> 2, t = lane & 3;

    const size_t base = (size_t)(w * 16 + h) * 2048;   // halves
    const float scale = 0.17677669529663687f;          // 32^-0.5

    const uint32_t qb = smem_u32(qs), kb = smem_u32(kss), vb = smem_u32(vst);
#pragma unroll
    for (int i = 0; i < 2; i++) {
        int c   = tid + i * 128;
        int row = c >> 2, cc = c & 3;
        uint32_t so = (uint32_t)(row * 20 + cc * 4) * 4u;
        CP_ASYNC16(qb + so, g_qh + base + row * 32 + cc * 8);
        CP_ASYNC16(kb + so, g_kh + base + row * 32 + cc * 8);
        int d = c >> 3, c2 = c & 7;
        CP_ASYNC16(vb + (uint32_t)(d * 36 + c2 * 4) * 4u, g_vh + base + d * 64 + c2 * 8);
    }
    CP_COMMIT();
    if (tid < 64) {
        int wIdx = w & 63;
        int hs = ((wIdx >> 3) << 3) | (tid >> 3);
        int ws = ((wIdx & 7) << 3) | (tid & 7);
        int rh = (hs < 56) ? 0 : (hs < 60 ? 1 : 2);
        int rw = (ws < 56) ? 0 : (ws < 60 ? 1 : 2);
        sid[tid] = rh * 3 + rw;
    }
    CP_WAIT0();
    __syncthreads();

    // S = q @ k^T  (hd=32 -> 2 k16 steps)
    const int m0 = wid * 16;
    float acc[8][4];
#pragma unroll
    for (int a = 0; a < 8; a++)
#pragma unroll
        for (int b = 0; b < 4; b++) acc[a][b] = 0.f;

#pragma unroll
    for (int ks = 0; ks < 2; ks++) {
        const int kk = ks * 8 + t;
        int ab = (m0 + g) * 20 + kk;
        uint32_t a0 = qs[ab], a1 = qs[ab + 160], a2 = qs[ab + 4], a3 = qs[ab + 164];
#pragma unroll
        for (int nf = 0; nf < 8; nf++) {
            int nb = (nf * 8 + g) * 20 + kk;
            MMAH(acc[nf], a0, a1, a2, a3, kss[nb], kss[nb + 4]);
        }
    }

    const float* bh = g_bias + h * 4096;
    const int r0 = m0 + g, r1 = r0 + 8;
    const int id0 = sid[r0], id1 = sid[r1];
    float mx0 = -1e30f, mx1 = -1e30f;
#pragma unroll
    for (int nf = 0; nf < 8; nf++) {
        int c0 = nf * 8 + 2 * t;
        int ic0 = sid[c0], ic1 = sid[c0 + 1];
        acc[nf][0] = fmaf(acc[nf][0], scale, bh[r0 * 64 + c0])     + (id0 != ic0 ? -100.f : 0.f);
        acc[nf][1] = fmaf(acc[nf][1], scale, bh[r0 * 64 + c0 + 1]) + (id0 != ic1 ? -100.f : 0.f);
        acc[nf][2] = fmaf(acc[nf][2], scale, bh[r1 * 64 + c0])     + (id1 != ic0 ? -100.f : 0.f);
        acc[nf][3] = fmaf(acc[nf][3], scale, bh[r1 * 64 + c0 + 1]) + (id1 != ic1 ? -100.f : 0.f);
        mx0 = fmaxf(mx0, fmaxf(acc[nf][0], acc[nf][1]));
        mx1 = fmaxf(mx1, fmaxf(acc[nf][2], acc[nf][3]));
    }
    mx0 = fmaxf(mx0, __shfl_xor_sync(0xffffffffu, mx0, 1));
    mx0 = fmaxf(mx0, __shfl_xor_sync(0xffffffffu, mx0, 2));
    mx1 = fmaxf(mx1, __shfl_xor_sync(0xffffffffu, mx1, 1));
    mx1 = fmaxf(mx1, __shfl_xor_sync(0xffffffffu, mx1, 2));
    float s0 = 0.f, s1 = 0.f;
#pragma unroll
    for (int nf = 0; nf < 8; nf++) {
        acc[nf][0] = __expf(acc[nf][0] - mx0); s0 += acc[nf][0];
        acc[nf][1] = __expf(acc[nf][1] - mx0); s0 += acc[nf][1];
        acc[nf][2] = __expf(acc[nf][2] - mx1); s1 += acc[nf][2];
        acc[nf][3] = __expf(acc[nf][3] - mx1); s1 += acc[nf][3];
    }
    s0 += __shfl_xor_sync(0xffffffffu, s0, 1);
    s0 += __shfl_xor_sync(0xffffffffu, s0, 2);
    s1 += __shfl_xor_sync(0xffffffffu, s1, 1);
    s1 += __shfl_xor_sync(0xffffffffu, s1, 2);
    const float inv0 = 1.f / s0, inv1 = 1.f / s1;

    // O = P @ V: P packed straight from C-fragments into k16 A-operands.
    float acc2[4][4];
#pragma unroll
    for (int a = 0; a < 4; a++)
#pragma unroll
        for (int b = 0; b < 4; b++) acc2[a][b] = 0.f;
#pragma unroll
    for (int j = 0; j < 4; j++) {
        uint32_t a0 = pack2h(acc[2 * j][0] * inv0,     acc[2 * j][1] * inv0);
        uint32_t a1 = pack2h(acc[2 * j][2] * inv1,     acc[2 * j][3] * inv1);
        uint32_t a2 = pack2h(acc[2 * j + 1][0] * inv0, acc[2 * j + 1][1] * inv0);
        uint32_t a3 = pack2h(acc[2 * j + 1][2] * inv1, acc[2 * j + 1][3] * inv1);
        const int kk = j * 8 + t;
#pragma unroll
        for (int nf = 0; nf < 4; nf++) {
            int nb = (nf * 8 + g) * 36 + kk;
            MMAH(acc2[nf], a0, a1, a2, a3, vst[nb], vst[nb + 4]);
        }
    }

    __syncthreads();
    float* ost = (float*)sm;  // 64*36 = 2304 f32
#pragma unroll
    for (int nf = 0; nf < 4; nf++) {
        int c0 = nf * 8 + 2 * t;
        ost[r0 * 36 + c0]     = acc2[nf][0];
        ost[r0 * 36 + c0 + 1] = acc2[nf][1];
        ost[r1 * 36 + c0]     = acc2[nf][2];
        ost[r1 * 36 + c0 + 1] = acc2[nf][3];
    }
    __syncthreads();
    const size_t ob = (size_t)(w * 64) * 512 + h * 32;
#pragma unroll
    for (int i = 0; i < 16; i++) {
        int idx = tid + i * 128;
        int row = idx >> 5, d = idx & 31;
        g_atth[ob + (size_t)row * 512 + d] = __float2half(ost[row * 36 + d]);
    }
}

// ---------------- launch ----------------
extern "C" void kernel_launch(void* const* d_in, const int* in_sizes, int n_in,
                              void* d_out, int out_size) {
    const float* x  = nullptr;  // 33554432
    const float* qw = nullptr;  // 786432
    const float* qb = nullptr;  // 1536
    const float* pw = nullptr;  // 262144
    const float* pb = nullptr;  // 512
    const float* bt = nullptr;  // 3600
    const int*   ri = nullptr;  // 4096
    for (int i = 0; i < n_in; i++) {
        switch (in_sizes[i]) {
            case 33554432: x  = (const float*)d_in[i]; break;
            case 786432:   qw = (const float*)d_in[i]; break;
            case 1536:     qb = (const float*)d_in[i]; break;
            case 262144:   pw = (const float*)d_in[i]; break;
            case 512:      pb = (const float*)d_in[i]; break;
            case 3600:     bt = (const float*)d_in[i]; break;
            case 4096:     ri = (const int*)d_in[i];   break;
            default: break;
        }
    }
    float* out = (float*)d_out;

    k_pre<<<8448, 1024>>>(x, qw, pw);
    k_bias_pre<<<16, 256>>>(bt, ri);
    k_gemm<true><<<dim3(12, 512), 128>>>(qb, nullptr);
    k_attn<<<dim3(1024, 16), 128>>>();
    k_gemm<false><<<dim3(4, 512), 128>>>(pb, out);
}

// round 13
// speedup vs baseline: 1.6670x; 1.0186x over previous
#include <cuda_runtime.h>
#include <cuda_fp16.h>
#include <cstdint>

// ---------------- problem constants ----------------
// B=16, H=W=64, C=512, NH=16, hd=32, WS=8, N=64, SS=4

// ---------------- device scratch ----------------
__device__ __half g_xh[33554432];              // fp16 query (pre-rounded)
__device__ __half g_wqh[786432];               // fp16 qkv_w
__device__ __half g_wph[262144];               // fp16 proj_w
__device__ __half g_atth[33554432];            // fp16 attention output
__device__ __half g_qh[1024 * 16 * 64 * 32];   // [(w,h,n),d]
__device__ __half g_kh[1024 * 16 * 64 * 32];   // [(w,h,n),d]
__device__ __half g_vh[1024 * 16 * 64 * 32];   // [(w,h,d),n]  (transposed)
__device__ float  g_bias[16 * 64 * 64];

// ---------------- helpers ----------------
__device__ __forceinline__ uint32_t pack2h(float lo, float hi) {
    uint32_t r;
    asm("cvt.rn.f16x2.f32 %0, %1, %2;" : "=r"(r) : "f"(hi), "f"(lo));
    return r;
}

__device__ __forceinline__ uint32_t smem_u32(const void* p) {
    uint32_t r;
    asm("{ .reg .u64 t; cvta.to.shared.u64 t, %1; cvt.u32.u64 %0, t; }"
        : "=r"(r) : "l"(p));
    return r;
}

// fp16 MMA, fp32 accumulate: D(16x8) += A(16x16) * B(16x8)
#define MMAH(c, a0, a1, a2, a3, b0, b1)                                      \
    asm volatile(                                                            \
        "mma.sync.aligned.m16n8k16.row.col.f32.f16.f16.f32 "                 \
        "{%0,%1,%2,%3}, {%4,%5,%6,%7}, {%8,%9}, {%0,%1,%2,%3};\n"            \
        : "+f"((c)[0]), "+f"((c)[1]), "+f"((c)[2]), "+f"((c)[3])             \
        : "r"(a0), "r"(a1), "r"(a2), "r"(a3), "r"(b0), "r"(b1))

#define CP_ASYNC16(dst_u32, src_ptr)                                         \
    asm volatile("cp.async.cg.shared.global [%0], [%1], 16;" ::              \
                 "r"(dst_u32), "l"(src_ptr))
#define CP_COMMIT() asm volatile("cp.async.commit_group;")
#define CP_WAIT0()  asm volatile("cp.async.wait_group 0;")
#define CP_WAIT2()  asm volatile("cp.async.wait_group 2;")

// window-token row -> original image row (shift + window partition fused).
__device__ __forceinline__ int permute_row(int r) {
    int b   = r >> 12;
    int rem = r & 4095;
    int wi  = rem >> 6, n = rem & 63;
    int hs  = ((wi >> 3) << 3) | (n >> 3);
    int ws  = ((wi & 7) << 3) | (n & 7);
    int hp  = (hs + 4) & 63;
    int wp  = (ws + 4) & 63;
    return (b << 12) | (hp << 6) | wp;
}

// ---------------- K-1: pre-round x / qkv_w / proj_w to fp16 ----------------
__global__ __launch_bounds__(1024) void k_pre(const float* __restrict__ x,
                                              const float* __restrict__ qw,
                                              const float* __restrict__ pw) {
    int i = blockIdx.x * 1024 + threadIdx.x;  // float4 index, < 8650752
    float4 v;
    __half2* dst;
    if (i < 8388608) {
        v   = ((const float4*)x)[i];
        dst = (__half2*)g_xh + (size_t)i * 2;
    } else if (i < 8585216) {
        int j = i - 8388608;
        v   = ((const float4*)qw)[j];
        dst = (__half2*)g_wqh + (size_t)j * 2;
    } else {
        int j = i - 8585216;
        v   = ((const float4*)pw)[j];
        dst = (__half2*)g_wph + (size_t)j * 2;
    }
    dst[0] = __floats2half2_rn(v.x, v.y);
    dst[1] = __floats2half2_rn(v.z, v.w);
}

// ---------------- K0: expand relative-position bias ----------------
__global__ void k_bias_pre(const float* __restrict__ bt, const int* __restrict__ ri) {
    int h = blockIdx.x;  // 0..15
    for (int nm = threadIdx.x; nm < 4096; nm += blockDim.x)
        g_bias[h * 4096 + nm] = bt[ri[nm] * 16 + h];
}

// ---------------- K1/K3: fp16 GEMM (NT), 128x128x32, 128 thr -----------------
// 4 warps x 64x64 warp tile; 4-STAGE cp.async ring (3 tiles in flight,
// wait_group 2 + empty tail commits keep the outstanding count uniform).
// 2 CTAs/SM (128 thr, 80KB dynamic smem) -> cross-CTA latency hiding.
template <bool IS_QKV>
__global__ __launch_bounds__(128, 2) void k_gemm(const float* __restrict__ bias,
                                                 float* __restrict__ outp) {
    extern __shared__ uint32_t dsm[];   // 4 stages x (A 2560 + B 2560 b32) = 80KB

    const __half* Asrc = IS_QKV ? g_xh : g_atth;
    const __half* Wsrc = IS_QKV ? g_wqh : g_wph;

    const int Cb   = blockIdx.x * 128;   // column tile (fast axis)
    const int Rb   = blockIdx.y * 128;   // row tile
    const int tid  = threadIdx.x;
    const int lane = tid & 31, wid = tid >> 5;
    const int g = lane >> 2, t = lane & 3;
    const int wm = wid & 1, wn = wid >> 1;
    const int m0 = wm * 64, n0 = wn * 64;

    // cp.async: 512 chunks of 16B per matrix, 4/thread each
    const int lrow4 = tid >> 2, cc4 = tid & 3;
    const uint32_t sbase = smem_u32(dsm);

    int asrc_off[4], bsrc_off[4];
    uint32_t dstoff[4];
#pragma unroll
    for (int i = 0; i < 4; i++) {
        int row = lrow4 + i * 32;
        int src = IS_QKV ? permute_row(Rb + row) : (Rb + row);
        asrc_off[i] = src * 512 + cc4 * 8;
        bsrc_off[i] = (Cb + row) * 512 + cc4 * 8;
        dstoff[i]   = (uint32_t)(row * 20 + cc4 * 4) * 4u;
    }

    auto issue = [&](int j, int k0) {
        const uint32_t ab = sbase + (uint32_t)j * 20480u;
        const uint32_t bb = ab + 10240u;
#pragma unroll
        for (int i = 0; i < 4; i++)
            CP_ASYNC16(ab + dstoff[i], Asrc + asrc_off[i] + k0);
#pragma unroll
        for (int i = 0; i < 4; i++)
            CP_ASYNC16(bb + dstoff[i], Wsrc + bsrc_off[i] + k0);
        CP_COMMIT();
    };

    issue(0, 0); issue(1, 32); issue(2, 64);

    float acc[4][8][4];
#pragma unroll
    for (int a = 0; a < 4; a++)
#pragma unroll
        for (int b = 0; b < 8; b++)
#pragma unroll
            for (int cc = 0; cc < 4; cc++) acc[a][b][cc] = 0.f;

#pragma unroll 1
    for (int kt = 0; kt < 16; kt++) {
        CP_WAIT2();          // tile kt landed (kt+1, kt+2 may still fly)
        __syncthreads();     // all warps past kt-1 MMAs; data visible
        if (kt < 13) issue((kt + 3) & 3, (kt + 3) * 32);
        else CP_COMMIT();    // empty group: keeps outstanding count at 3

        const uint32_t* A = dsm + (kt & 3) * 5120;
        const uint32_t* B = A + 2560;
#pragma unroll
        for (int ks = 0; ks < 2; ks++) {
            const int kk = ks * 8 + t;
            uint32_t a[4][4];
#pragma unroll
            for (int mf = 0; mf < 4; mf++) {
                int base = (m0 + mf * 16 + g) * 20 + kk;
                a[mf][0] = A[base];
                a[mf][1] = A[base + 160];
                a[mf][2] = A[base + 4];
                a[mf][3] = A[base + 164];
            }
#pragma unroll
            for (int nf = 0; nf < 8; nf++) {
                int nb      = (n0 + nf * 8 + g) * 20 + kk;
                uint32_t b0 = B[nb], b1 = B[nb + 4];
#pragma unroll
                for (int mf = 0; mf < 4; mf++)
                    MMAH(acc[mf][nf], a[mf][0], a[mf][1], a[mf][2], a[mf][3], b0, b1);
            }
        }
    }
    __syncthreads();

    // epilogue: two 128x64 halves staged through smem
    float* st = (float*)dsm;  // 128*65 = 8320 f32 fits easily
#pragma unroll 1
    for (int hh = 0; hh < 2; hh++) {
        if (wn == hh) {
#pragma unroll
            for (int mf = 0; mf < 4; mf++)
#pragma unroll
                for (int nf = 0; nf < 8; nf++) {
                    int row = m0 + mf * 16 + g;
                    int col = nf * 8 + 2 * t;
                    st[row * 65 + col]           = acc[mf][nf][0];
                    st[row * 65 + col + 1]       = acc[mf][nf][1];
                    st[(row + 8) * 65 + col]     = acc[mf][nf][2];
                    st[(row + 8) * 65 + col + 1] = acc[mf][nf][3];
                }
        }
        __syncthreads();

        const int Co = Cb + hh * 64;
        if (IS_QKV) {
            const int s = Co >> 9;  // 0=q 1=k 2=v (uniform)
            if (s < 2) {
                __half* buf = (s == 0) ? g_qh : g_kh;
#pragma unroll
                for (int i = 0; i < 32; i++) {
                    int p  = tid + i * 128;
                    int m  = p >> 5, jj = (p & 31) * 2;
                    int r  = Rb + m, o = Co + jj;
                    int hd = (o >> 5) & 15, d = o & 31;
                    int wnd = r >> 6, n = r & 63;
                    float v0 = st[m * 65 + jj]     + bias[o];
                    float v1 = st[m * 65 + jj + 1] + bias[o + 1];
                    *(__half2*)&buf[((size_t)((wnd * 16 + hd) * 64 + n)) * 32 + d] =
                        __floats2half2_rn(v0, v1);
                }
            } else {
                // V transposed: [(w,h,d), n]; m-fast -> coalesced n
#pragma unroll
                for (int i = 0; i < 64; i++) {
                    int idx = tid + i * 128;
                    int m = idx & 127, jj = idx >> 7;
                    int r = Rb + m, o = Co + jj;
                    int hd = (o >> 5) & 15, d = o & 31;
                    int wnd = r >> 6, n = r & 63;
                    float v = st[m * 65 + jj] + bias[o];
                    g_vh[((size_t)((wnd * 16 + hd) * 32 + d)) * 64 + n] = __float2half(v);
                }
            }
        } else {
#pragma unroll
            for (int i = 0; i < 64; i++) {
                int idx = tid + i * 128;
                int m = idx >> 6, j = idx & 63;
                int r = Rb + m, o = Co + j;
                int dst = permute_row(r);
                outp[(size_t)dst * 512 + o] = st[m * 65 + j] + bias[o];
            }
        }
        __syncthreads();
    }
}

// ---------------- K2: attention (fp16 MMA), one block per (window, head) ----
__global__ __launch_bounds__(128) void k_attn() {
    __shared__ uint32_t sm[1280 + 1280 + 1152];
    __shared__ int sid[64];
    uint32_t* qs  = sm;
    uint32_t* kss = sm + 1280;
    uint32_t* vst = sm + 2560;

    const int w   = blockIdx.x;
    const int h   = blockIdx.y;
    const int tid = threadIdx.x;
    const int lane = tid & 31, wid = tid >> 5;
    const int g = lane >> 2, t = lane & 3;

    const size_t base = (size_t)(w * 16 + h) * 2048;   // halves
    const float scale = 0.17677669529663687f;          // 32^-0.5

    const uint32_t qb = smem_u32(qs), kb = smem_u32(kss), vb = smem_u32(vst);
#pragma unroll
    for (int i = 0; i < 2; i++) {
        int c   = tid + i * 128;
        int row = c >> 2, cc = c & 3;
        uint32_t so = (uint32_t)(row * 20 + cc * 4) * 4u;
        CP_ASYNC16(qb + so, g_qh + base + row * 32 + cc * 8);
        CP_ASYNC16(kb + so, g_kh + base + row * 32 + cc * 8);
        int d = c >> 3, c2 = c & 7;
        CP_ASYNC16(vb + (uint32_t)(d * 36 + c2 * 4) * 4u, g_vh + base + d * 64 + c2 * 8);
    }
    CP_COMMIT();
    if (tid < 64) {
        int wIdx = w & 63;
        int hs = ((wIdx >> 3) << 3) | (tid >> 3);
        int ws = ((wIdx & 7) << 3) | (tid & 7);
        int rh = (hs < 56) ? 0 : (hs < 60 ? 1 : 2);
        int rw = (ws < 56) ? 0 : (ws < 60 ? 1 : 2);
        sid[tid] = rh * 3 + rw;
    }
    CP_WAIT0();
    __syncthreads();

    // S = q @ k^T  (hd=32 -> 2 k16 steps)
    const int m0 = wid * 16;
    float acc[8][4];
#pragma unroll
    for (int a = 0; a < 8; a++)
#pragma unroll
        for (int b = 0; b < 4; b++) acc[a][b] = 0.f;

#pragma unroll
    for (int ks = 0; ks < 2; ks++) {
        const int kk = ks * 8 + t;
        int ab = (m0 + g) * 20 + kk;
        uint32_t a0 = qs[ab], a1 = qs[ab + 160], a2 = qs[ab + 4], a3 = qs[ab + 164];
#pragma unroll
        for (int nf = 0; nf < 8; nf++) {
            int nb = (nf * 8 + g) * 20 + kk;
            MMAH(acc[nf], a0, a1, a2, a3, kss[nb], kss[nb + 4]);
        }
    }

    const float* bh = g_bias + h * 4096;
    const int r0 = m0 + g, r1 = r0 + 8;
    const int id0 = sid[r0], id1 = sid[r1];
    float mx0 = -1e30f, mx1 = -1e30f;
#pragma unroll
    for (int nf = 0; nf < 8; nf++) {
        int c0 = nf * 8 + 2 * t;
        int ic0 = sid[c0], ic1 = sid[c0 + 1];
        acc[nf][0] = fmaf(acc[nf][0], scale, bh[r0 * 64 + c0])     + (id0 != ic0 ? -100.f : 0.f);
        acc[nf][1] = fmaf(acc[nf][1], scale, bh[r0 * 64 + c0 + 1]) + (id0 != ic1 ? -100.f : 0.f);
        acc[nf][2] = fmaf(acc[nf][2], scale, bh[r1 * 64 + c0])     + (id1 != ic0 ? -100.f : 0.f);
        acc[nf][3] = fmaf(acc[nf][3], scale, bh[r1 * 64 + c0 + 1]) + (id1 != ic1 ? -100.f : 0.f);
        mx0 = fmaxf(mx0, fmaxf(acc[nf][0], acc[nf][1]));
        mx1 = fmaxf(mx1, fmaxf(acc[nf][2], acc[nf][3]));
    }
    mx0 = fmaxf(mx0, __shfl_xor_sync(0xffffffffu, mx0, 1));
    mx0 = fmaxf(mx0, __shfl_xor_sync(0xffffffffu, mx0, 2));
    mx1 = fmaxf(mx1, __shfl_xor_sync(0xffffffffu, mx1, 1));
    mx1 = fmaxf(mx1, __shfl_xor_sync(0xffffffffu, mx1, 2));
    float s0 = 0.f, s1 = 0.f;
#pragma unroll
    for (int nf = 0; nf < 8; nf++) {
        acc[nf][0] = __expf(acc[nf][0] - mx0); s0 += acc[nf][0];
        acc[nf][1] = __expf(acc[nf][1] - mx0); s0 += acc[nf][1];
        acc[nf][2] = __expf(acc[nf][2] - mx1); s1 += acc[nf][2];
        acc[nf][3] = __expf(acc[nf][3] - mx1); s1 += acc[nf][3];
    }
    s0 += __shfl_xor_sync(0xffffffffu, s0, 1);
    s0 += __shfl_xor_sync(0xffffffffu, s0, 2);
    s1 += __shfl_xor_sync(0xffffffffu, s1, 1);
    s1 += __shfl_xor_sync(0xffffffffu, s1, 2);
    const float inv0 = 1.f / s0, inv1 = 1.f / s1;

    // O = P @ V: P packed straight from C-fragments into k16 A-operands.
    float acc2[4][4];
#pragma unroll
    for (int a = 0; a < 4; a++)
#pragma unroll
        for (int b = 0; b < 4; b++) acc2[a][b] = 0.f;
#pragma unroll
    for (int j = 0; j < 4; j++) {
        uint32_t a0 = pack2h(acc[2 * j][0] * inv0,     acc[2 * j][1] * inv0);
        uint32_t a1 = pack2h(acc[2 * j][2] * inv1,     acc[2 * j][3] * inv1);
        uint32_t a2 = pack2h(acc[2 * j + 1][0] * inv0, acc[2 * j + 1][1] * inv0);
        uint32_t a3 = pack2h(acc[2 * j + 1][2] * inv1, acc[2 * j + 1][3] * inv1);
        const int kk = j * 8 + t;
#pragma unroll
        for (int nf = 0; nf < 4; nf++) {
            int nb = (nf * 8 + g) * 36 + kk;
            MMAH(acc2[nf], a0, a1, a2, a3, vst[nb], vst[nb + 4]);
        }
    }

    __syncthreads();  // everyone done reading qs/kss/vst before reuse
    // fp16 staging: [64 rows][20 b32], half2 col = c0/2 = nf*4+t (conflict-free)
    uint32_t* osth = sm;
#pragma unroll
    for (int nf = 0; nf < 4; nf++) {
        int col = nf * 4 + t;
        osth[r0 * 20 + col] = pack2h(acc2[nf][0], acc2[nf][1]);
        osth[r1 * 20 + col] = pack2h(acc2[nf][2], acc2[nf][3]);
    }
    __syncthreads();
    // store: 64 rows x 16 half2, coalesced per row
    __half2* outh2 = (__half2*)g_atth;
    const size_t ob2 = (size_t)(w * 64) * 256 + h * 16;
#pragma unroll
    for (int i = 0; i < 8; i++) {
        int idx = tid + i * 128;
        int row = idx >> 4, col = idx & 15;
        outh2[ob2 + (size_t)row * 256 + col] = *(__half2*)&osth[row * 20 + col];
    }
}

// ---------------- launch ----------------
static constexpr int SMEM_GEMM_BYTES = 4 * 5120 * 4;  // 81920

extern "C" void kernel_launch(void* const* d_in, const int* in_sizes, int n_in,
                              void* d_out, int out_size) {
    const float* x  = nullptr;  // 33554432
    const float* qw = nullptr;  // 786432
    const float* qb = nullptr;  // 1536
    const float* pw = nullptr;  // 262144
    const float* pb = nullptr;  // 512
    const float* bt = nullptr;  // 3600
    const int*   ri = nullptr;  // 4096
    for (int i = 0; i < n_in; i++) {
        switch (in_sizes[i]) {
            case 33554432: x  = (const float*)d_in[i]; break;
            case 786432:   qw = (const float*)d_in[i]; break;
            case 1536:     qb = (const float*)d_in[i]; break;
            case 262144:   pw = (const float*)d_in[i]; break;
            case 512:      pb = (const float*)d_in[i]; break;
            case 3600:     bt = (const float*)d_in[i]; break;
            case 4096:     ri = (const int*)d_in[i];   break;
            default: break;
        }
    }
    float* out = (float*)d_out;

    cudaFuncSetAttribute(k_gemm<true>, cudaFuncAttributeMaxDynamicSharedMemorySize,
                         SMEM_GEMM_BYTES);
    cudaFuncSetAttribute(k_gemm<false>, cudaFuncAttributeMaxDynamicSharedMemorySize,
                         SMEM_GEMM_BYTES);

    k_pre<<<8448, 1024>>>(x, qw, pw);
    k_bias_pre<<<16, 256>>>(bt, ri);
    k_gemm<true><<<dim3(12, 512), 128, SMEM_GEMM_BYTES>>>(qb, nullptr);
    k_attn<<<dim3(1024, 16), 128>>>();
    k_gemm<false><<<dim3(4, 512), 128, SMEM_GEMM_BYTES>>>(pb, out);
}

// round 14
// speedup vs baseline: 1.7044x; 1.0224x over previous
#include <cuda_runtime.h>
#include <cuda_fp16.h>
#include <cstdint>

// ---------------- problem constants ----------------
// B=16, H=W=64, C=512, NH=16, hd=32, WS=8, N=64, SS=4

// ---------------- device scratch ----------------
__device__ __half g_xh[33554432];              // fp16 query (pre-rounded)
__device__ __half g_wqh[786432];               // fp16 qkv_w
__device__ __half g_wph[262144];               // fp16 proj_w
__device__ __half g_atth[33554432];            // fp16 attention output
__device__ __half g_qh[1024 * 16 * 64 * 32];   // [(w,h,n),d]
__device__ __half g_kh[1024 * 16 * 64 * 32];   // [(w,h,n),d]
__device__ __half g_vh[1024 * 16 * 64 * 32];   // [(w,h,d),n]  (transposed)
__device__ __half g_bm[4 * 16 * 64 * 64];      // fused bias+mask [cls][h][n][m]
__device__ float  g_bias[16 * 64 * 64];        // fp32 bias (GEMM epilogues unused)

// ---------------- helpers ----------------
__device__ __forceinline__ uint32_t pack2h(float lo, float hi) {
    uint32_t r;
    asm("cvt.rn.f16x2.f32 %0, %1, %2;" : "=r"(r) : "f"(hi), "f"(lo));
    return r;
}

__device__ __forceinline__ uint32_t smem_u32(const void* p) {
    uint32_t r;
    asm("{ .reg .u64 t; cvta.to.shared.u64 t, %1; cvt.u32.u64 %0, t; }"
        : "=r"(r) : "l"(p));
    return r;
}

// fp16 MMA, fp32 accumulate: D(16x8) += A(16x16) * B(16x8)
#define MMAH(c, a0, a1, a2, a3, b0, b1)                                      \
    asm volatile(                                                            \
        "mma.sync.aligned.m16n8k16.row.col.f32.f16.f16.f32 "                 \
        "{%0,%1,%2,%3}, {%4,%5,%6,%7}, {%8,%9}, {%0,%1,%2,%3};\n"            \
        : "+f"((c)[0]), "+f"((c)[1]), "+f"((c)[2]), "+f"((c)[3])             \
        : "r"(a0), "r"(a1), "r"(a2), "r"(a3), "r"(b0), "r"(b1))

#define CP_ASYNC16(dst_u32, src_ptr)                                         \
    asm volatile("cp.async.cg.shared.global [%0], [%1], 16;" ::              \
                 "r"(dst_u32), "l"(src_ptr))
#define CP_COMMIT() asm volatile("cp.async.commit_group;")
#define CP_WAIT0()  asm volatile("cp.async.wait_group 0;")
#define CP_WAIT2()  asm volatile("cp.async.wait_group 2;")

// window-token row -> original image row (shift + window partition fused).
__device__ __forceinline__ int permute_row(int r) {
    int b   = r >> 12;
    int rem = r & 4095;
    int wi  = rem >> 6, n = rem & 63;
    int hs  = ((wi >> 3) << 3) | (n >> 3);
    int ws  = ((wi & 7) << 3) | (n & 7);
    int hp  = (hs + 4) & 63;
    int wp  = (ws + 4) & 63;
    return (b << 12) | (hp << 6) | wp;
}

// ---------------- K-1: pre-round x / qkv_w / proj_w to fp16 ----------------
__global__ __launch_bounds__(1024) void k_pre(const float* __restrict__ x,
                                              const float* __restrict__ qw,
                                              const float* __restrict__ pw) {
    int i = blockIdx.x * 1024 + threadIdx.x;  // float4 index, < 8650752
    float4 v;
    __half2* dst;
    if (i < 8388608) {
        v   = ((const float4*)x)[i];
        dst = (__half2*)g_xh + (size_t)i * 2;
    } else if (i < 8585216) {
        int j = i - 8388608;
        v   = ((const float4*)qw)[j];
        dst = (__half2*)g_wqh + (size_t)j * 2;
    } else {
        int j = i - 8585216;
        v   = ((const float4*)pw)[j];
        dst = (__half2*)g_wph + (size_t)j * 2;
    }
    dst[0] = __floats2half2_rn(v.x, v.y);
    dst[1] = __floats2half2_rn(v.z, v.w);
}

// ---------------- K0: build fused bias+mask fp16 table --------------------
// blockIdx.x = window class (bit1: wi_h==7, bit0: wi_w==7), blockIdx.y = head
__global__ __launch_bounds__(256) void k_bias_pre(const float* __restrict__ bt,
                                                  const int* __restrict__ ri) {
    const int cls = blockIdx.x, h = blockIdx.y;
    __shared__ int sid[64];
    if (threadIdx.x < 64) {
        int tok = threadIdx.x;
        int rh = (cls & 2) ? (((tok >> 3) < 4) ? 1 : 2) : 0;
        int rw = (cls & 1) ? (((tok & 7) < 4) ? 1 : 2) : 0;
        sid[tok] = rh * 3 + rw;
    }
    __syncthreads();
    __half* dst = g_bm + (((size_t)cls * 16 + h) << 12);
    for (int nm = threadIdx.x; nm < 4096; nm += 256) {
        int n = nm >> 6, m = nm & 63;
        float v = bt[ri[nm] * 16 + h] + ((sid[n] != sid[m]) ? -100.f : 0.f);
        dst[nm] = __float2half(v);
    }
}

// ---------------- K1/K3: fp16 GEMM (NT), 128x128x32, 128 thr -----------------
// 4 warps x 64x64 warp tile; 4-STAGE cp.async ring (3 tiles in flight).
// 2 CTAs/SM -> cross-CTA latency hiding. (R13 config, unchanged.)
template <bool IS_QKV>
__global__ __launch_bounds__(128, 2) void k_gemm(const float* __restrict__ bias,
                                                 float* __restrict__ outp) {
    extern __shared__ uint32_t dsm[];   // 4 stages x (A 2560 + B 2560 b32) = 80KB

    const __half* Asrc = IS_QKV ? g_xh : g_atth;
    const __half* Wsrc = IS_QKV ? g_wqh : g_wph;

    const int Cb   = blockIdx.x * 128;   // column tile (fast axis)
    const int Rb   = blockIdx.y * 128;   // row tile
    const int tid  = threadIdx.x;
    const int lane = tid & 31, wid = tid >> 5;
    const int g = lane >> 2, t = lane & 3;
    const int wm = wid & 1, wn = wid >> 1;
    const int m0 = wm * 64, n0 = wn * 64;

    const int lrow4 = tid >> 2, cc4 = tid & 3;
    const uint32_t sbase = smem_u32(dsm);

    int asrc_off[4], bsrc_off[4];
    uint32_t dstoff[4];
#pragma unroll
    for (int i = 0; i < 4; i++) {
        int row = lrow4 + i * 32;
        int src = IS_QKV ? permute_row(Rb + row) : (Rb + row);
        asrc_off[i] = src * 512 + cc4 * 8;
        bsrc_off[i] = (Cb + row) * 512 + cc4 * 8;
        dstoff[i]   = (uint32_t)(row * 20 + cc4 * 4) * 4u;
    }

    auto issue = [&](int j, int k0) {
        const uint32_t ab = sbase + (uint32_t)j * 20480u;
        const uint32_t bb = ab + 10240u;
#pragma unroll
        for (int i = 0; i < 4; i++)
            CP_ASYNC16(ab + dstoff[i], Asrc + asrc_off[i] + k0);
#pragma unroll
        for (int i = 0; i < 4; i++)
            CP_ASYNC16(bb + dstoff[i], Wsrc + bsrc_off[i] + k0);
        CP_COMMIT();
    };

    issue(0, 0); issue(1, 32); issue(2, 64);

    float acc[4][8][4];
#pragma unroll
    for (int a = 0; a < 4; a++)
#pragma unroll
        for (int b = 0; b < 8; b++)
#pragma unroll
            for (int cc = 0; cc < 4; cc++) acc[a][b][cc] = 0.f;

#pragma unroll 1
    for (int kt = 0; kt < 16; kt++) {
        CP_WAIT2();
        __syncthreads();
        if (kt < 13) issue((kt + 3) & 3, (kt + 3) * 32);
        else CP_COMMIT();

        const uint32_t* A = dsm + (kt & 3) * 5120;
        const uint32_t* B = A + 2560;
#pragma unroll
        for (int ks = 0; ks < 2; ks++) {
            const int kk = ks * 8 + t;
            uint32_t a[4][4];
#pragma unroll
            for (int mf = 0; mf < 4; mf++) {
                int base = (m0 + mf * 16 + g) * 20 + kk;
                a[mf][0] = A[base];
                a[mf][1] = A[base + 160];
                a[mf][2] = A[base + 4];
                a[mf][3] = A[base + 164];
            }
#pragma unroll
            for (int nf = 0; nf < 8; nf++) {
                int nb      = (n0 + nf * 8 + g) * 20 + kk;
                uint32_t b0 = B[nb], b1 = B[nb + 4];
#pragma unroll
                for (int mf = 0; mf < 4; mf++)
                    MMAH(acc[mf][nf], a[mf][0], a[mf][1], a[mf][2], a[mf][3], b0, b1);
            }
        }
    }
    __syncthreads();

    float* st = (float*)dsm;  // 128*65 = 8320 f32
#pragma unroll 1
    for (int hh = 0; hh < 2; hh++) {
        if (wn == hh) {
#pragma unroll
            for (int mf = 0; mf < 4; mf++)
#pragma unroll
                for (int nf = 0; nf < 8; nf++) {
                    int row = m0 + mf * 16 + g;
                    int col = nf * 8 + 2 * t;
                    st[row * 65 + col]           = acc[mf][nf][0];
                    st[row * 65 + col + 1]       = acc[mf][nf][1];
                    st[(row + 8) * 65 + col]     = acc[mf][nf][2];
                    st[(row + 8) * 65 + col + 1] = acc[mf][nf][3];
                }
        }
        __syncthreads();

        const int Co = Cb + hh * 64;
        if (IS_QKV) {
            const int s = Co >> 9;  // 0=q 1=k 2=v (uniform)
            if (s < 2) {
                __half* buf = (s == 0) ? g_qh : g_kh;
#pragma unroll
                for (int i = 0; i < 32; i++) {
                    int p  = tid + i * 128;
                    int m  = p >> 5, jj = (p & 31) * 2;
                    int r  = Rb + m, o = Co + jj;
                    int hd = (o >> 5) & 15, d = o & 31;
                    int wnd = r >> 6, n = r & 63;
                    float v0 = st[m * 65 + jj]     + bias[o];
                    float v1 = st[m * 65 + jj + 1] + bias[o + 1];
                    *(__half2*)&buf[((size_t)((wnd * 16 + hd) * 64 + n)) * 32 + d] =
                        __floats2half2_rn(v0, v1);
                }
            } else {
#pragma unroll
                for (int i = 0; i < 64; i++) {
                    int idx = tid + i * 128;
                    int m = idx & 127, jj = idx >> 7;
                    int r = Rb + m, o = Co + jj;
                    int hd = (o >> 5) & 15, d = o & 31;
                    int wnd = r >> 6, n = r & 63;
                    float v = st[m * 65 + jj] + bias[o];
                    g_vh[((size_t)((wnd * 16 + hd) * 32 + d)) * 64 + n] = __float2half(v);
                }
            }
        } else {
#pragma unroll
            for (int i = 0; i < 64; i++) {
                int idx = tid + i * 128;
                int m = idx >> 6, j = idx & 63;
                int r = Rb + m, o = Co + j;
                int dst = permute_row(r);
                outp[(size_t)dst * 512 + o] = st[m * 65 + j] + bias[o];
            }
        }
        __syncthreads();
    }
}

// ---------------- K2: attention (fp16 MMA), one block per (window, head) ----
__global__ __launch_bounds__(128) void k_attn() {
    __shared__ uint32_t sm[1280 + 1280 + 1152];
    uint32_t* qs  = sm;
    uint32_t* kss = sm + 1280;
    uint32_t* vst = sm + 2560;

    const int w   = blockIdx.x;
    const int h   = blockIdx.y;
    const int tid = threadIdx.x;
    const int lane = tid & 31, wid = tid >> 5;
    const int g = lane >> 2, t = lane & 3;

    const size_t base = (size_t)(w * 16 + h) * 2048;   // halves
    const float scale = 0.17677669529663687f;          // 32^-0.5

    const uint32_t qb = smem_u32(qs), kb = smem_u32(kss), vb = smem_u32(vst);
#pragma unroll
    for (int i = 0; i < 2; i++) {
        int c   = tid + i * 128;
        int row = c >> 2, cc = c & 3;
        uint32_t so = (uint32_t)(row * 20 + cc * 4) * 4u;
        CP_ASYNC16(qb + so, g_qh + base + row * 32 + cc * 8);
        CP_ASYNC16(kb + so, g_kh + base + row * 32 + cc * 8);
        int d = c >> 3, c2 = c & 7;
        CP_ASYNC16(vb + (uint32_t)(d * 36 + c2 * 4) * 4u, g_vh + base + d * 64 + c2 * 8);
    }
    CP_COMMIT();

    // fused bias+mask table pointer (half2): class from window position
    const int wIdx = w & 63;
    const int cls  = (((wIdx >> 3) == 7) ? 2 : 0) | (((wIdx & 7) == 7) ? 1 : 0);
    const __half2* bh2 = (const __half2*)g_bm + (((size_t)cls * 16 + h) << 11);

    CP_WAIT0();
    __syncthreads();

    // S = q @ k^T  (hd=32 -> 2 k16 steps)
    const int m0 = wid * 16;
    float acc[8][4];
#pragma unroll
    for (int a = 0; a < 8; a++)
#pragma unroll
        for (int b = 0; b < 4; b++) acc[a][b] = 0.f;

#pragma unroll
    for (int ks = 0; ks < 2; ks++) {
        const int kk = ks * 8 + t;
        int ab = (m0 + g) * 20 + kk;
        uint32_t a0 = qs[ab], a1 = qs[ab + 160], a2 = qs[ab + 4], a3 = qs[ab + 164];
#pragma unroll
        for (int nf = 0; nf < 8; nf++) {
            int nb = (nf * 8 + g) * 20 + kk;
            MMAH(acc[nf], a0, a1, a2, a3, kss[nb], kss[nb + 4]);
        }
    }

    // scale + fused (bias+mask), softmax (rows r0/r1 per lane)
    const int r0 = m0 + g, r1 = r0 + 8;
    float mx0 = -1e30f, mx1 = -1e30f;
#pragma unroll
    for (int nf = 0; nf < 8; nf++) {
        float2 b0 = __half22float2(bh2[r0 * 32 + nf * 4 + t]);
        float2 b1 = __half22float2(bh2[r1 * 32 + nf * 4 + t]);
        acc[nf][0] = fmaf(acc[nf][0], scale, b0.x);
        acc[nf][1] = fmaf(acc[nf][1], scale, b0.y);
        acc[nf][2] = fmaf(acc[nf][2], scale, b1.x);
        acc[nf][3] = fmaf(acc[nf][3], scale, b1.y);
        mx0 = fmaxf(mx0, fmaxf(acc[nf][0], acc[nf][1]));
        mx1 = fmaxf(mx1, fmaxf(acc[nf][2], acc[nf][3]));
    }
    mx0 = fmaxf(mx0, __shfl_xor_sync(0xffffffffu, mx0, 1));
    mx0 = fmaxf(mx0, __shfl_xor_sync(0xffffffffu, mx0, 2));
    mx1 = fmaxf(mx1, __shfl_xor_sync(0xffffffffu, mx1, 1));
    mx1 = fmaxf(mx1, __shfl_xor_sync(0xffffffffu, mx1, 2));
    float s0 = 0.f, s1 = 0.f;
#pragma unroll
    for (int nf = 0; nf < 8; nf++) {
        acc[nf][0] = __expf(acc[nf][0] - mx0); s0 += acc[nf][0];
        acc[nf][1] = __expf(acc[nf][1] - mx0); s0 += acc[nf][1];
        acc[nf][2] = __expf(acc[nf][2] - mx1); s1 += acc[nf][2];
        acc[nf][3] = __expf(acc[nf][3] - mx1); s1 += acc[nf][3];
    }
    s0 += __shfl_xor_sync(0xffffffffu, s0, 1);
    s0 += __shfl_xor_sync(0xffffffffu, s0, 2);
    s1 += __shfl_xor_sync(0xffffffffu, s1, 1);
    s1 += __shfl_xor_sync(0xffffffffu, s1, 2);
    const float inv0 = 1.f / s0, inv1 = 1.f / s1;

    // O = P @ V: P packed straight from C-fragments into k16 A-operands.
    float acc2[4][4];
#pragma unroll
    for (int a = 0; a < 4; a++)
#pragma unroll
        for (int b = 0; b < 4; b++) acc2[a][b] = 0.f;
#pragma unroll
    for (int j = 0; j < 4; j++) {
        uint32_t a0 = pack2h(acc[2 * j][0] * inv0,     acc[2 * j][1] * inv0);
        uint32_t a1 = pack2h(acc[2 * j][2] * inv1,     acc[2 * j][3] * inv1);
        uint32_t a2 = pack2h(acc[2 * j + 1][0] * inv0, acc[2 * j + 1][1] * inv0);
        uint32_t a3 = pack2h(acc[2 * j + 1][2] * inv1, acc[2 * j + 1][3] * inv1);
        const int kk = j * 8 + t;
#pragma unroll
        for (int nf = 0; nf < 4; nf++) {
            int nb = (nf * 8 + g) * 36 + kk;
            MMAH(acc2[nf], a0, a1, a2, a3, vst[nb], vst[nb + 4]);
        }
    }

    __syncthreads();
    uint32_t* osth = sm;  // fp16 staging [64][20 b32]
#pragma unroll
    for (int nf = 0; nf < 4; nf++) {
        int col = nf * 4 + t;
        osth[r0 * 20 + col] = pack2h(acc2[nf][0], acc2[nf][1]);
        osth[r1 * 20 + col] = pack2h(acc2[nf][2], acc2[nf][3]);
    }
    __syncthreads();
    __half2* outh2 = (__half2*)g_atth;
    const size_t ob2 = (size_t)(w * 64) * 256 + h * 16;
#pragma unroll
    for (int i = 0; i < 8; i++) {
        int idx = tid + i * 128;
        int row = idx >> 4, col = idx & 15;
        outh2[ob2 + (size_t)row * 256 + col] = *(__half2*)&osth[row * 20 + col];
    }
}

// ---------------- launch ----------------
static constexpr int SMEM_GEMM_BYTES = 4 * 5120 * 4;  // 81920

extern "C" void kernel_launch(void* const* d_in, const int* in_sizes, int n_in,
                              void* d_out, int out_size) {
    const float* x  = nullptr;  // 33554432
    const float* qw = nullptr;  // 786432
    const float* qb = nullptr;  // 1536
    const float* pw = nullptr;  // 262144
    const float* pb = nullptr;  // 512
    const float* bt = nullptr;  // 3600
    const int*   ri = nullptr;  // 4096
    for (int i = 0; i < n_in; i++) {
        switch (in_sizes[i]) {
            case 33554432: x  = (const float*)d_in[i]; break;
            case 786432:   qw = (const float*)d_in[i]; break;
            case 1536:     qb = (const float*)d_in[i]; break;
            case 262144:   pw = (const float*)d_in[i]; break;
            case 512:      pb = (const float*)d_in[i]; break;
            case 3600:     bt = (const float*)d_in[i]; break;
            case 4096:     ri = (const int*)d_in[i];   break;
            default: break;
        }
    }
    float* out = (float*)d_out;

    cudaFuncSetAttribute(k_gemm<true>, cudaFuncAttributeMaxDynamicSharedMemorySize,
                         SMEM_GEMM_BYTES);
    cudaFuncSetAttribute(k_gemm<false>, cudaFuncAttributeMaxDynamicSharedMemorySize,
                         SMEM_GEMM_BYTES);

    k_pre<<<8448, 1024>>>(x, qw, pw);
    k_bias_pre<<<dim3(4, 16), 256>>>(bt, ri);
    k_gemm<true><<<dim3(12, 512), 128, SMEM_GEMM_BYTES>>>(qb, nullptr);
    k_attn<<<dim3(1024, 16), 128>>>();
    k_gemm<false><<<dim3(4, 512), 128, SMEM_GEMM_BYTES>>>(pb, out);
}